// round 12
// baseline (speedup 1.0000x reference)
#include <cuda_runtime.h>
#include <cuda_fp16.h>
#include <math.h>
#include <float.h>
#include <stdint.h>

#define TT 2048
#define HIDDEN 2048
#define NH 32
#define NKV 4
#define HD 128
#define QS (NH*HD)        // 4096
#define KVS (NKV*HD)      // 512
#define QKVN (QS + 2*KVS) // 5120

// ---------------- scratch (static device globals; no allocs) ----------------
__device__ __half g_q   [(size_t)NH * TT * HD];   //  16 MB [h][t][d]  (pre-scaled by d^-1/2 * log2e)
__device__ __half g_k   [(size_t)NKV * TT * HD];  //   2 MB [kv][t][d]
__device__ __half g_vt  [(size_t)NKV * HD * TT];  //   2 MB [kv][d][t]
__device__ __half g_attn[(size_t)TT * QS];        //  16 MB [t][h*128+d]
__device__ __half g_hidh [(size_t)TT * HIDDEN];   //   8 MB fp16(hidden)
__device__ __half g_wqkvh[(size_t)QKVN * HIDDEN]; //  20 MB fp16(w_qkv)
__device__ __half g_woh  [(size_t)HIDDEN * QS];   //  16 MB fp16(w_o)
__device__ float  g_invf[64];

#define ATT_SCALE 0.08838834764831845f
#define LOG2E 1.4426950408889634f
#define EXP_SHIFT_L2 5.7707801635558535f   // 4 * log2(e)

// ---------------- helpers ----------------
__device__ __forceinline__ uint32_t smem_u32(const void* p) {
    uint32_t a;
    asm("{ .reg .u64 t; cvta.to.shared.u64 t, %1; cvt.u32.u64 %0, t; }" : "=r"(a) : "l"(p));
    return a;
}
__device__ __forceinline__ void cp16(uint32_t dst, const void* src) {
    asm volatile("cp.async.cg.shared.global [%0], [%1], 16;" :: "r"(dst), "l"(src));
}
__device__ __forceinline__ void mma_f16(float* d, const unsigned* a, const unsigned* b) {
    asm volatile(
        "mma.sync.aligned.m16n8k16.row.col.f32.f16.f16.f32 "
        "{%0,%1,%2,%3}, {%4,%5,%6,%7}, {%8,%9}, {%0,%1,%2,%3};\n"
        : "+f"(d[0]), "+f"(d[1]), "+f"(d[2]), "+f"(d[3])
        : "r"(a[0]), "r"(a[1]), "r"(a[2]), "r"(a[3]), "r"(b[0]), "r"(b[1]));
}
__device__ __forceinline__ void ldsm4(unsigned* r, uint32_t addr) {
    asm volatile("ldmatrix.sync.aligned.m8n8.x4.shared.b16 {%0,%1,%2,%3}, [%4];"
        : "=r"(r[0]), "=r"(r[1]), "=r"(r[2]), "=r"(r[3]) : "r"(addr));
}
__device__ __forceinline__ float ex2f(float x) {
    float y;
    asm("ex2.approx.f32 %0, %1;" : "=f"(y) : "f"(x));
    return y;
}

// ================= dense fp16 TN GEMM, 256x128 CTA tile, 512 threads =================
// smem: A stages 3 x 32KB at 0; B stages 3 x 16KB at 98304. Total 147456.
// mode 1 epilogue buf: 256 x 132 fp32 = 135168 B (reuses stage space).
#define STAGES 3
#define GSM_A_STAGE 32768
#define GSM_B_OFF   98304
#define GSM_B_STAGE 16384
#define SM_TOT      147456
#define BM 256
#define BN 128

// mode 0: plain fp32 C out
// mode 1: fused QKV epilogue: bn = head (0-31 q, 32-35 k, 36-39 v)
__global__ __launch_bounds__(512, 1) void gemm_h(
    const __half* __restrict__ A, const __half* __restrict__ B, float* __restrict__ C,
    int K, int lda, int ldb, int ldc, float scale,
    const int* __restrict__ positions, const float* __restrict__ qw,
    const float* __restrict__ kw, int mode)
{
    int bm = blockIdx.y, bn = blockIdx.x;

    extern __shared__ char smem[];
    uint32_t sbase = smem_u32(smem);

    int tid  = threadIdx.x;
    int warp = tid >> 5, lane = tid & 31;
    int wm = warp & 7, wn = warp >> 3;   // 8 x 2 warp grid (m x n)
    int r = lane >> 2, c = lane & 3;

    // ldmatrix lane geometry
    int arow_in = ((lane >> 3) & 1) * 8 + (lane & 7);
    int ahi = lane >> 4;
    int am7 = lane & 7;
    int bro = ((lane >> 4) << 3) + (lane & 7);
    int bcb = (lane >> 3) & 1;
    int bb7 = lane & 7;

    float acc[2][8][4];
#pragma unroll
    for (int i = 0; i < 2; i++)
#pragma unroll
        for (int j = 0; j < 8; j++)
#pragma unroll
            for (int k = 0; k < 4; k++) acc[i][j][k] = 0.f;

    int nkt = K >> 6;
    const __half* Ab = A + (long long)bm * BM * lda;
    const __half* Bb = B + (long long)bn * BN * ldb;

    // staging: A: 256 rows x 8 chunks = 2048 cp16 -> 4/thread (row=tid>>1, chunks (tid&1)*4+0..3)
    //          B: 128 rows x 8 chunks = 1024 cp16 -> 2/thread (row=tid>>2, chunks (tid&3)*2+0..1)
    int smA = tid >> 1;
    int scA = (tid & 1) * 4;
    int smB = tid >> 2;
    int scB = (tid & 3) * 2;
    long long arow = (long long)smA * lda;
    long long brow = (long long)smB * ldb;

#pragma unroll
    for (int p = 0; p < STAGES - 1; p++) {
        if (p < nkt) {
            int kb = p << 6;
            uint32_t aD = sbase + p * GSM_A_STAGE + smA * 128;
            uint32_t bD = sbase + GSM_B_OFF + p * GSM_B_STAGE + smB * 128;
            const __half* as = Ab + arow + kb + scA * 8;
            const __half* bs = Bb + brow + kb + scB * 8;
#pragma unroll
            for (int j = 0; j < 4; j++) {
                int sw = ((scA + j) ^ (smA & 7)) * 16;
                cp16(aD + sw, as + j * 8);
            }
#pragma unroll
            for (int j = 0; j < 2; j++) {
                int sw = ((scB + j) ^ (smB & 7)) * 16;
                cp16(bD + sw, bs + j * 8);
            }
        }
        asm volatile("cp.async.commit_group;" ::: "memory");
    }

    for (int kt = 0; kt < nkt; kt++) {
        asm volatile("cp.async.wait_group 1;" ::: "memory");
        __syncthreads();

        if (kt + STAGES - 1 < nkt) {
            int kn = kt + STAGES - 1;
            int kb = kn << 6;
            uint32_t aD = sbase + (kn % STAGES) * GSM_A_STAGE + smA * 128;
            uint32_t bD = sbase + GSM_B_OFF + (kn % STAGES) * GSM_B_STAGE + smB * 128;
            const __half* as = Ab + arow + kb + scA * 8;
            const __half* bs = Bb + brow + kb + scB * 8;
#pragma unroll
            for (int j = 0; j < 4; j++) {
                int sw = ((scA + j) ^ (smA & 7)) * 16;
                cp16(aD + sw, as + j * 8);
            }
#pragma unroll
            for (int j = 0; j < 2; j++) {
                int sw = ((scB + j) ^ (smB & 7)) * 16;
                cp16(bD + sw, bs + j * 8);
            }
        }
        asm volatile("cp.async.commit_group;" ::: "memory");

        uint32_t sa  = sbase + (kt % STAGES) * GSM_A_STAGE;
        uint32_t sbm = sbase + GSM_B_OFF + (kt % STAGES) * GSM_B_STAGE;

#pragma unroll
        for (int ks = 0; ks < 4; ks++) {
            unsigned a[2][4];
#pragma unroll
            for (int mt = 0; mt < 2; mt++) {
                uint32_t row = (uint32_t)(wm * 32 + mt * 16 + arow_in);
                ldsm4(a[mt], sa + row * 128u + ((unsigned)((2 * ks + ahi) ^ am7) << 4));
            }
#pragma unroll
            for (int ntp = 0; ntp < 4; ntp++) {
                unsigned bb[4];
                uint32_t row = (uint32_t)(wn * 64 + ntp * 16 + bro);
                ldsm4(bb, sbm + row * 128u + ((unsigned)((2 * ks + bcb) ^ bb7) << 4));
#pragma unroll
                for (int mt = 0; mt < 2; mt++) {
                    mma_f16(acc[mt][2 * ntp],     a[mt], bb);
                    mma_f16(acc[mt][2 * ntp + 1], a[mt], bb + 2);
                }
            }
        }
    }

    asm volatile("cp.async.wait_group 0;" ::: "memory");

    if (mode == 0) {
#pragma unroll
        for (int mt = 0; mt < 2; mt++) {
            int m0 = bm * BM + wm * 32 + mt * 16 + r;
#pragma unroll
            for (int nt = 0; nt < 8; nt++) {
                int n0 = bn * BN + wn * 64 + nt * 8 + 2 * c;
                *(float2*)(C + (long long)m0 * ldc + n0) =
                    make_float2(acc[mt][nt][0] * scale, acc[mt][nt][1] * scale);
                *(float2*)(C + (long long)(m0 + 8) * ldc + n0) =
                    make_float2(acc[mt][nt][2] * scale, acc[mt][nt][3] * scale);
            }
        }
        return;
    }

    // ---- fused QKV epilogue: acc -> smem buf (256 x 132 fp32), then norm/rope/transpose ----
    __syncthreads();
    float* buf = (float*)smem;
#pragma unroll
    for (int mt = 0; mt < 2; mt++) {
        int mrow = wm * 32 + mt * 16 + r;
#pragma unroll
        for (int nt = 0; nt < 8; nt++) {
            int nc = wn * 64 + nt * 8 + 2 * c;
            *(float2*)(buf + mrow * 132 + nc)       = make_float2(acc[mt][nt][0], acc[mt][nt][1]);
            *(float2*)(buf + (mrow + 8) * 132 + nc) = make_float2(acc[mt][nt][2], acc[mt][nt][3]);
        }
    }
    __syncthreads();

    int h = bn;
    if (h < 36) {
        int row = tid >> 1, half = tid & 1;     // 512 threads = 256 rows x 2 halves
        int t = bm * BM + row;
        const float* own = buf + row * 132 + half * 64;
        const float* par = buf + row * 132 + (half ^ 1) * 64;

        float ss = 0.f;
#pragma unroll
        for (int i = 0; i < 16; i++) {
            float4 v = *(const float4*)(own + i * 4);
            ss += v.x * v.x + v.y * v.y + v.z * v.z + v.w * v.w;
        }
        ss += __shfl_xor_sync(0xffffffffu, ss, 1);
        float rinv = rsqrtf(ss * (1.f / 128.f) + 1e-6f);

        const float* w_ = (h < 32) ? qw : kw;
        float pos = (float)positions[t];
        float osc = (h < 32) ? (ATT_SCALE * LOG2E) : 1.f;
        float sgn = half ? 1.f : -1.f;
        __half* outp;
        if (h < 32) outp = g_q + ((size_t)h * TT + t) * HD + half * 64;
        else        outp = g_k + ((size_t)(h - 32) * TT + t) * HD + half * 64;

#pragma unroll 8
        for (int i = 0; i < 64; i += 2) {
            float cs0 = 0.f, sn0 = 0.f, cs1 = 0.f, sn1 = 0.f;
            if (!(lane & 1)) {
                float a0 = pos * g_invf[i], a1 = pos * g_invf[i + 1];
                cs0 = cosf(a0); sn0 = sinf(a0);
                cs1 = cosf(a1); sn1 = sinf(a1);
            }
            cs0 = __shfl_sync(0xffffffffu, cs0, lane & ~1);
            sn0 = __shfl_sync(0xffffffffu, sn0, lane & ~1);
            cs1 = __shfl_sync(0xffffffffu, cs1, lane & ~1);
            sn1 = __shfl_sync(0xffffffffu, sn1, lane & ~1);
            float y0 = own[i]     * rinv * w_[half * 64 + i];
            float y1 = own[i + 1] * rinv * w_[half * 64 + i + 1];
            float z0 = par[i]     * rinv * w_[(half ^ 1) * 64 + i];
            float z1 = par[i + 1] * rinv * w_[(half ^ 1) * 64 + i + 1];
            float o0 = (y0 * cs0 + sgn * z0 * sn0) * osc;
            float o1 = (y1 * cs1 + sgn * z1 * sn1) * osc;
            *(__half2*)(outp + i) = __floats2half2_rn(o0, o1);
        }
    } else {
        int d = tid >> 2, quarter = tid & 3;   // 512 threads = 128 d x 4 token-quarters
        int kvh = h - 36;
        __half* vp = g_vt + ((size_t)kvh * HD + d) * TT + (size_t)bm * BM + quarter * 64;
#pragma unroll 8
        for (int j2 = 0; j2 < 64; j2 += 2) {
            float v0 = buf[(quarter * 64 + j2) * 132 + d];
            float v1 = buf[(quarter * 64 + j2 + 1) * 132 + d];
            *(__half2*)(vp + j2) = __floats2half2_rn(v0, v1);
        }
    }
}

// ================= fused flash attention (interleaved exp/PV) =================
#define FSM_Q 0
#define FSM_K 32768
#define FSM_V (32768 + 65536)
#define FSM_L (FSM_V + 65536)
#define FSM_TOT (FSM_L + 1024 + 128)

__device__ __forceinline__ void flash_load_tile128(
    uint32_t sdst, const __half* src, int ld, int tid)
{
#pragma unroll
    for (int i = 0; i < 4; i++) {
        int li = tid + 512 * i;
        int row = li >> 4, cc = li & 15;
        uint32_t dst = sdst + (cc >> 3) * 16384 + row * 128 + (((cc & 7) ^ (row & 7)) * 16);
        cp16(dst, src + (long long)row * ld + cc * 8);
    }
}

__global__ __launch_bounds__(512, 1) void flash_kernel()
{
    int b = blockIdx.x;
    int bm = 15 - (b >> 5);     // heavy blocks first
    int h  = b & 31;
    int kvh = h >> 3;

    extern __shared__ char sm[];
    uint32_t sbase = smem_u32(sm);
    float* lsum = (float*)(sm + FSM_L);

    int tid = threadIdx.x;
    int w = tid >> 5, lane = tid & 31;
    int wm = w & 7, wn = w >> 3;
    int r = lane >> 2, c = lane & 3;

    int am  = wm * 16 + ((lane >> 3) & 1) * 8 + (lane & 7);
    int am7 = am & 7;
    int ahi = lane >> 4;
    uint32_t aoff = (uint32_t)am * 128u;
    int bro = ((lane >> 4) << 3) + (lane & 7);
    int bcb = (lane >> 3) & 1;
    int bb7 = bro & 7;

    const __half* qsrc = g_q + ((size_t)h * TT + (size_t)bm * 128) * HD;
    const __half* ksrc = g_k + (size_t)kvh * TT * HD;
    const __half* vsrc = g_vt + (size_t)kvh * HD * TT;

    flash_load_tile128(sbase + FSM_Q, qsrc, HD, tid);
    flash_load_tile128(sbase + FSM_K, ksrc, HD, tid);
#pragma unroll
    for (int i = 0; i < 4; i++) {
        int li = tid + 512 * i;
        int row = li >> 4, cc = li & 15;
        uint32_t dst = sbase + FSM_V + (cc >> 3) * 16384 + row * 128 + (((cc & 7) ^ (row & 7)) * 16);
        cp16(dst, vsrc + (size_t)row * TT + cc * 8);
    }
    asm volatile("cp.async.commit_group;" ::: "memory");

    float acc_o[16][4];
#pragma unroll
    for (int i = 0; i < 16; i++)
#pragma unroll
        for (int k = 0; k < 4; k++) acc_o[i][k] = 0.f;
    float l0a = 0.f, l0b = 0.f, l1a = 0.f, l1b = 0.f;

    int mrow0 = wm * 16 + r;

    for (int j = 0; j <= bm; j++) {
        int st = j & 1;
        asm volatile("cp.async.wait_group 0;" ::: "memory");
        __syncthreads();

        if (j < bm) {
            int jn = j + 1;
            flash_load_tile128(sbase + FSM_K + (st ^ 1) * 32768,
                               ksrc + (size_t)jn * 128 * HD, HD, tid);
#pragma unroll
            for (int i = 0; i < 4; i++) {
                int li = tid + 512 * i;
                int row = li >> 4, cc = li & 15;
                uint32_t dst = sbase + FSM_V + (st ^ 1) * 32768 + (cc >> 3) * 16384
                             + row * 128 + (((cc & 7) ^ (row & 7)) * 16);
                cp16(dst, vsrc + (size_t)row * TT + jn * 128 + cc * 8);
            }
        }
        asm volatile("cp.async.commit_group;" ::: "memory");

        // ---- S = Q @ K^T (Q pre-scaled by d^-1/2 * log2e) ----
        float acc_s[8][4];
#pragma unroll
        for (int i = 0; i < 8; i++)
#pragma unroll
            for (int k = 0; k < 4; k++) acc_s[i][k] = 0.f;

        uint32_t squ = sbase + FSM_Q;
        uint32_t sku = sbase + FSM_K + st * 32768;
#pragma unroll
        for (int kt = 0; kt < 2; kt++) {
#pragma unroll
            for (int ks = 0; ks < 4; ks++) {
                unsigned a[4];
                ldsm4(a, squ + kt * 16384 + aoff + ((unsigned)((2 * ks + ahi) ^ am7) << 4));
#pragma unroll
                for (int ntp = 0; ntp < 4; ntp++) {
                    unsigned bb[4];
                    ldsm4(bb, sku + kt * 16384 + (unsigned)(wn * 64 + ntp * 16 + bro) * 128
                              + ((unsigned)((2 * ks + bcb) ^ bb7) << 4));
                    mma_f16(acc_s[2 * ntp],     a, bb);
                    mma_f16(acc_s[2 * ntp + 1], a, bb + 2);
                }
            }
        }

        // ---- interleaved exp2/mask/pack + PV mma (per ks-chunk) ----
        bool diag = (j == bm);
        uint32_t svu = sbase + FSM_V + st * 32768 + wn * 16384;
#pragma unroll
        for (int ks = 0; ks < 4; ks++) {
            unsigned a[4];
#pragma unroll
            for (int q = 0; q < 2; q++) {
                int nt = 2 * ks + q;
                int n0 = wn * 64 + nt * 8 + 2 * c;
                float v0 = ex2f(acc_s[nt][0] - EXP_SHIFT_L2);
                float v1 = ex2f(acc_s[nt][1] - EXP_SHIFT_L2);
                float v2 = ex2f(acc_s[nt][2] - EXP_SHIFT_L2);
                float v3 = ex2f(acc_s[nt][3] - EXP_SHIFT_L2);
                if (diag) {
                    if (n0     > mrow0)     v0 = 0.f;
                    if (n0 + 1 > mrow0)     v1 = 0.f;
                    if (n0     > mrow0 + 8) v2 = 0.f;
                    if (n0 + 1 > mrow0 + 8) v3 = 0.f;
                }
                if (q == 0) { l0a += v0 + v1; l1a += v2 + v3; }
                else        { l0b += v0 + v1; l1b += v2 + v3; }
                __half2 h01 = __floats2half2_rn(v0, v1);
                __half2 h23 = __floats2half2_rn(v2, v3);
                a[2 * q]     = *(unsigned*)&h01;
                a[2 * q + 1] = *(unsigned*)&h23;
            }
#pragma unroll
            for (int dnp = 0; dnp < 8; dnp++) {
                unsigned bb[4];
                ldsm4(bb, svu + (unsigned)(dnp * 16 + bro) * 128
                          + ((unsigned)((2 * ks + bcb) ^ bb7) << 4));
                mma_f16(acc_o[2 * dnp],     a, bb);
                mma_f16(acc_o[2 * dnp + 1], a, bb + 2);
            }
        }
    }

    // ---- cross-slice reduction + normalize + write ----
    __syncthreads();
    float* red = (float*)(sm + FSM_K);

    if (wn == 1) {
        float* dst = red + wm * 2048;
#pragma unroll
        for (int dn = 0; dn < 16; dn++) {
            *(float2*)(dst + r * 128 + dn * 8 + 2 * c)       = make_float2(acc_o[dn][0], acc_o[dn][1]);
            *(float2*)(dst + (r + 8) * 128 + dn * 8 + 2 * c) = make_float2(acc_o[dn][2], acc_o[dn][3]);
        }
    }
    float l0 = l0a + l0b, l1 = l1a + l1b;
    l0 += __shfl_xor_sync(0xffffffffu, l0, 1);
    l0 += __shfl_xor_sync(0xffffffffu, l0, 2);
    l1 += __shfl_xor_sync(0xffffffffu, l1, 1);
    l1 += __shfl_xor_sync(0xffffffffu, l1, 2);
    if (c == 0) {
        lsum[wn * 128 + wm * 16 + r]     = l0;
        lsum[wn * 128 + wm * 16 + r + 8] = l1;
    }
    __syncthreads();

    if (wn == 0) {
        int row0 = wm * 16 + r;
        float inv0 = 1.f / (lsum[row0]     + lsum[128 + row0]);
        float inv1 = 1.f / (lsum[row0 + 8] + lsum[128 + row0 + 8]);
        const float* src = red + wm * 2048;
        __half* o0 = g_attn + (size_t)(bm * 128 + row0) * QS + h * 128;
        __half* o1 = g_attn + (size_t)(bm * 128 + row0 + 8) * QS + h * 128;
#pragma unroll
        for (int dn = 0; dn < 16; dn++) {
            int nc = dn * 8 + 2 * c;
            float2 s0 = *(const float2*)(src + r * 128 + nc);
            float2 s1 = *(const float2*)(src + (r + 8) * 128 + nc);
            *(__half2*)(o0 + nc) = __floats2half2_rn((acc_o[dn][0] + s0.x) * inv0,
                                                     (acc_o[dn][1] + s0.y) * inv0);
            *(__half2*)(o1 + nc) = __floats2half2_rn((acc_o[dn][2] + s1.x) * inv1,
                                                     (acc_o[dn][3] + s1.y) * inv1);
        }
    }
}

// ---------------- fp32 -> fp16 conversion (all three arrays, one launch) ----------------
#define N4_HID  (TT * HIDDEN / 4)
#define N4_WQKV (QKVN * HIDDEN / 4)
#define N4_WO   (HIDDEN * QS / 4)
__global__ void h_conv_all(const float4* __restrict__ s0, uint2* __restrict__ d0,
                           const float4* __restrict__ s1, uint2* __restrict__ d1,
                           const float4* __restrict__ s2, uint2* __restrict__ d2) {
    int i = blockIdx.x * 256 + threadIdx.x;
    int stride = gridDim.x * 256;
    int ntot = N4_HID + N4_WQKV + N4_WO;
    for (; i < ntot; i += stride) {
        const float4* s; uint2* d; int idx;
        if (i < N4_HID)              { s = s0; d = d0; idx = i; }
        else if (i < N4_HID + N4_WQKV) { s = s1; d = d1; idx = i - N4_HID; }
        else                         { s = s2; d = d2; idx = i - N4_HID - N4_WQKV; }
        float4 v = s[idx];
        __half2 lo = __floats2half2_rn(v.x, v.y);
        __half2 hi = __floats2half2_rn(v.z, v.w);
        uint2 o;
        o.x = *(unsigned*)&lo;
        o.y = *(unsigned*)&hi;
        d[idx] = o;
    }
}

// ---------------- inv_freq ----------------
__global__ void init_invf() {
    int i = threadIdx.x;
    if (i < 64)
        g_invf[i] = (float)exp(-(double)i * (log(10000.0) / 64.0));
}

// ---------------- launcher ----------------
extern "C" void kernel_launch(void* const* d_in, const int* in_sizes, int n_in,
                              void* d_out, int out_size)
{
    const int* positions = (const int*)d_in[0];   // int32 (JAX x64 disabled)
    const float* hidden = (const float*)d_in[1];
    const float* w_qkv  = (const float*)d_in[2];
    const float* w_o    = (const float*)d_in[3];
    const float* qw     = (const float*)d_in[4];
    const float* kw     = (const float*)d_in[5];
    float* out = (float*)d_out;

    __half *p_attn, *p_hidh, *p_wqkvh, *p_woh;
    cudaGetSymbolAddress((void**)&p_attn,  g_attn);
    cudaGetSymbolAddress((void**)&p_hidh,  g_hidh);
    cudaGetSymbolAddress((void**)&p_wqkvh, g_wqkvh);
    cudaGetSymbolAddress((void**)&p_woh,   g_woh);

    cudaFuncSetAttribute(gemm_h, cudaFuncAttributeMaxDynamicSharedMemorySize, SM_TOT);
    cudaFuncSetAttribute(flash_kernel, cudaFuncAttributeMaxDynamicSharedMemorySize, FSM_TOT);

    init_invf<<<1, 64>>>();

    // 0) fp16 conversions (one launch)
    h_conv_all<<<2048, 256>>>((const float4*)hidden, (uint2*)p_hidh,
                              (const float4*)w_qkv,  (uint2*)p_wqkvh,
                              (const float4*)w_o,    (uint2*)p_woh);

    // 1) QKV projection with fused RMSNorm+RoPE+reorder epilogue (256-row blocks)
    gemm_h<<<dim3(QKVN / BN, TT / BM, 1), 512, SM_TOT>>>(
        p_hidh, p_wqkvh, nullptr, HIDDEN, HIDDEN, HIDDEN, 0, 1.0f,
        positions, qw, kw, 1);

    // 2) fused flash attention -> g_attn (fp16)
    flash_kernel<<<512, 512, FSM_TOT>>>();

    // 3) output projection (fp32 out)
    gemm_h<<<dim3(HIDDEN / BN, TT / BM, 1), 512, SM_TOT>>>(
        p_attn, p_woh, out, QS, QS, QS, HIDDEN, 1.0f,
        nullptr, nullptr, nullptr, 0);
}

// round 13
// speedup vs baseline: 1.0598x; 1.0598x over previous
#include <cuda_runtime.h>
#include <cuda_fp16.h>
#include <math.h>
#include <float.h>
#include <stdint.h>

#define TT 2048
#define HIDDEN 2048
#define NH 32
#define NKV 4
#define HD 128
#define QS (NH*HD)        // 4096
#define KVS (NKV*HD)      // 512
#define QKVN (QS + 2*KVS) // 5120

// ---------------- scratch (static device globals; no allocs) ----------------
__device__ __half g_q   [(size_t)NH * TT * HD];   //  16 MB [h][t][d]  (pre-scaled by d^-1/2 * log2e)
__device__ __half g_k   [(size_t)NKV * TT * HD];  //   2 MB [kv][t][d]
__device__ __half g_vt  [(size_t)NKV * HD * TT];  //   2 MB [kv][d][t]
__device__ __half g_attn[(size_t)TT * QS];        //  16 MB [t][h*128+d]
__device__ __half g_hidh [(size_t)TT * HIDDEN];   //   8 MB fp16(hidden)
__device__ __half g_wqkvh[(size_t)QKVN * HIDDEN]; //  20 MB fp16(w_qkv)
__device__ __half g_woh  [(size_t)HIDDEN * QS];   //  16 MB fp16(w_o)
__device__ float  g_invf[64];

#define ATT_SCALE 0.08838834764831845f
#define LOG2E 1.4426950408889634f
#define EXP_SHIFT_L2 5.7707801635558535f   // 4 * log2(e)

// ---------------- helpers ----------------
__device__ __forceinline__ uint32_t smem_u32(const void* p) {
    uint32_t a;
    asm("{ .reg .u64 t; cvta.to.shared.u64 t, %1; cvt.u32.u64 %0, t; }" : "=r"(a) : "l"(p));
    return a;
}
__device__ __forceinline__ void cp16(uint32_t dst, const void* src) {
    asm volatile("cp.async.cg.shared.global [%0], [%1], 16;" :: "r"(dst), "l"(src));
}
__device__ __forceinline__ void mma_f16(float* d, const unsigned* a, const unsigned* b) {
    asm volatile(
        "mma.sync.aligned.m16n8k16.row.col.f32.f16.f16.f32 "
        "{%0,%1,%2,%3}, {%4,%5,%6,%7}, {%8,%9}, {%0,%1,%2,%3};\n"
        : "+f"(d[0]), "+f"(d[1]), "+f"(d[2]), "+f"(d[3])
        : "r"(a[0]), "r"(a[1]), "r"(a[2]), "r"(a[3]), "r"(b[0]), "r"(b[1]));
}
__device__ __forceinline__ void ldsm4(unsigned* r, uint32_t addr) {
    asm volatile("ldmatrix.sync.aligned.m8n8.x4.shared.b16 {%0,%1,%2,%3}, [%4];"
        : "=r"(r[0]), "=r"(r[1]), "=r"(r[2]), "=r"(r[3]) : "r"(addr));
}
__device__ __forceinline__ float ex2f(float x) {
    float y;
    asm("ex2.approx.f32 %0, %1;" : "=f"(y) : "f"(x));
    return y;
}

// ================= dense fp16 TN GEMM (R11 shape: 128x128, 256 thr, 2 CTA/SM) =================
#define STAGES 3
#define TILE_BYTES 16384
#define STAGE_BYTES 32768
#define SM_TOT (STAGES*STAGE_BYTES + 512)
#define BM 128
#define BN 128

// mode 0: plain fp32 C out
// mode 1: fused QKV epilogue: bn = head (0-31 q, 32-35 k, 36-39 v)
__global__ __launch_bounds__(256, 2) void gemm_h(
    const __half* __restrict__ A, const __half* __restrict__ B, float* __restrict__ C,
    int K, int lda, int ldb, int ldc, float scale,
    const int* __restrict__ positions, const float* __restrict__ qw,
    const float* __restrict__ kw, int mode)
{
    int bm = blockIdx.y, bn = blockIdx.x;

    extern __shared__ char smem[];
    uint32_t sbase = smem_u32(smem);

    int tid  = threadIdx.x;
    int warp = tid >> 5, lane = tid & 31;
    int wm = warp & 3, wn = warp >> 2;
    int r = lane >> 2, c = lane & 3;

    int arow_in = ((lane >> 3) & 1) * 8 + (lane & 7);
    int ahi = lane >> 4;
    int am7 = lane & 7;
    int bro = ((lane >> 4) << 3) + (lane & 7);
    int bcb = (lane >> 3) & 1;
    int bb7 = lane & 7;

    float acc[2][8][4];
#pragma unroll
    for (int i = 0; i < 2; i++)
#pragma unroll
        for (int j = 0; j < 8; j++)
#pragma unroll
            for (int k = 0; k < 4; k++) acc[i][j][k] = 0.f;

    int nkt = K >> 6;
    const __half* Ab = A + (long long)bm * BM * lda;
    const __half* Bb = B + (long long)bn * BN * ldb;

    int sm_ = tid >> 1;
    int scb = (tid & 1) * 4;
    long long arow = (long long)sm_ * lda;
    long long brow = (long long)sm_ * ldb;

#pragma unroll
    for (int p = 0; p < STAGES - 1; p++) {
        if (p < nkt) {
            int kb = p << 6;
            uint32_t aD = sbase + p * STAGE_BYTES + sm_ * 128;
            uint32_t bD = aD + TILE_BYTES;
            const __half* as = Ab + arow + kb + scb * 8;
            const __half* bs = Bb + brow + kb + scb * 8;
#pragma unroll
            for (int j = 0; j < 4; j++) {
                int sw = ((scb + j) ^ (sm_ & 7)) * 16;
                cp16(aD + sw, as + j * 8);
                cp16(bD + sw, bs + j * 8);
            }
        }
        asm volatile("cp.async.commit_group;" ::: "memory");
    }

    for (int kt = 0; kt < nkt; kt++) {
        asm volatile("cp.async.wait_group 1;" ::: "memory");
        __syncthreads();

        if (kt + STAGES - 1 < nkt) {
            int kn = kt + STAGES - 1;
            int kb = kn << 6;
            uint32_t aD = sbase + (kn % STAGES) * STAGE_BYTES + sm_ * 128;
            uint32_t bD = aD + TILE_BYTES;
            const __half* as = Ab + arow + kb + scb * 8;
            const __half* bs = Bb + brow + kb + scb * 8;
#pragma unroll
            for (int j = 0; j < 4; j++) {
                int sw = ((scb + j) ^ (sm_ & 7)) * 16;
                cp16(aD + sw, as + j * 8);
                cp16(bD + sw, bs + j * 8);
            }
        }
        asm volatile("cp.async.commit_group;" ::: "memory");

        uint32_t sa  = sbase + (kt % STAGES) * STAGE_BYTES;
        uint32_t sbm = sa + TILE_BYTES;

#pragma unroll
        for (int ks = 0; ks < 4; ks++) {
            unsigned a[2][4];
#pragma unroll
            for (int mt = 0; mt < 2; mt++) {
                uint32_t row = (uint32_t)(wm * 32 + mt * 16 + arow_in);
                ldsm4(a[mt], sa + row * 128u + ((unsigned)((2 * ks + ahi) ^ am7) << 4));
            }
#pragma unroll
            for (int ntp = 0; ntp < 4; ntp++) {
                unsigned bb[4];
                uint32_t row = (uint32_t)(wn * 64 + ntp * 16 + bro);
                ldsm4(bb, sbm + row * 128u + ((unsigned)((2 * ks + bcb) ^ bb7) << 4));
#pragma unroll
                for (int mt = 0; mt < 2; mt++) {
                    mma_f16(acc[mt][2 * ntp],     a[mt], bb);
                    mma_f16(acc[mt][2 * ntp + 1], a[mt], bb + 2);
                }
            }
        }
    }

    asm volatile("cp.async.wait_group 0;" ::: "memory");

    if (mode == 0) {
#pragma unroll
        for (int mt = 0; mt < 2; mt++) {
            int m0 = bm * BM + wm * 32 + mt * 16 + r;
#pragma unroll
            for (int nt = 0; nt < 8; nt++) {
                int n0 = bn * BN + wn * 64 + nt * 8 + 2 * c;
                *(float2*)(C + (long long)m0 * ldc + n0) =
                    make_float2(acc[mt][nt][0] * scale, acc[mt][nt][1] * scale);
                *(float2*)(C + (long long)(m0 + 8) * ldc + n0) =
                    make_float2(acc[mt][nt][2] * scale, acc[mt][nt][3] * scale);
            }
        }
        return;
    }

    // ---- fused QKV epilogue: acc -> smem buf (128 x 132 fp32), then norm/rope/transpose ----
    __syncthreads();
    float* buf = (float*)smem;
#pragma unroll
    for (int mt = 0; mt < 2; mt++) {
        int mrow = wm * 32 + mt * 16 + r;
#pragma unroll
        for (int nt = 0; nt < 8; nt++) {
            int nc = wn * 64 + nt * 8 + 2 * c;
            *(float2*)(buf + mrow * 132 + nc)       = make_float2(acc[mt][nt][0], acc[mt][nt][1]);
            *(float2*)(buf + (mrow + 8) * 132 + nc) = make_float2(acc[mt][nt][2], acc[mt][nt][3]);
        }
    }
    __syncthreads();

    int h = bn;
    if (h < 36) {
        int row = tid >> 1, half = tid & 1;
        int t = bm * BM + row;
        const float* own = buf + row * 132 + half * 64;
        const float* par = buf + row * 132 + (half ^ 1) * 64;

        float ss = 0.f;
#pragma unroll
        for (int i = 0; i < 16; i++) {
            float4 v = *(const float4*)(own + i * 4);
            ss += v.x * v.x + v.y * v.y + v.z * v.z + v.w * v.w;
        }
        ss += __shfl_xor_sync(0xffffffffu, ss, 1);
        float rinv = rsqrtf(ss * (1.f / 128.f) + 1e-6f);

        const float* w_ = (h < 32) ? qw : kw;
        float pos = (float)positions[t];
        float osc = (h < 32) ? (ATT_SCALE * LOG2E) : 1.f;
        float sgn = half ? 1.f : -1.f;
        __half* outp;
        if (h < 32) outp = g_q + ((size_t)h * TT + t) * HD + half * 64;
        else        outp = g_k + ((size_t)(h - 32) * TT + t) * HD + half * 64;

#pragma unroll 8
        for (int i = 0; i < 64; i += 2) {
            float cs0 = 0.f, sn0 = 0.f, cs1 = 0.f, sn1 = 0.f;
            if (!(lane & 1)) {
                float a0 = pos * g_invf[i], a1 = pos * g_invf[i + 1];
                cs0 = cosf(a0); sn0 = sinf(a0);
                cs1 = cosf(a1); sn1 = sinf(a1);
            }
            cs0 = __shfl_sync(0xffffffffu, cs0, lane & ~1);
            sn0 = __shfl_sync(0xffffffffu, sn0, lane & ~1);
            cs1 = __shfl_sync(0xffffffffu, cs1, lane & ~1);
            sn1 = __shfl_sync(0xffffffffu, sn1, lane & ~1);
            float y0 = own[i]     * rinv * w_[half * 64 + i];
            float y1 = own[i + 1] * rinv * w_[half * 64 + i + 1];
            float z0 = par[i]     * rinv * w_[(half ^ 1) * 64 + i];
            float z1 = par[i + 1] * rinv * w_[(half ^ 1) * 64 + i + 1];
            float o0 = (y0 * cs0 + sgn * z0 * sn0) * osc;
            float o1 = (y1 * cs1 + sgn * z1 * sn1) * osc;
            *(__half2*)(outp + i) = __floats2half2_rn(o0, o1);
        }
    } else {
        int d = tid >> 1, thalf = tid & 1;
        int kvh = h - 36;
        __half* vp = g_vt + ((size_t)kvh * HD + d) * TT + (size_t)bm * BM + thalf * 64;
#pragma unroll 8
        for (int j2 = 0; j2 < 64; j2 += 2) {
            float v0 = buf[(thalf * 64 + j2) * 132 + d];
            float v1 = buf[(thalf * 64 + j2 + 1) * 132 + d];
            *(__half2*)(vp + j2) = __floats2half2_rn(v0, v1);
        }
    }
}

// ================= fused flash attention: q-tile 64, 256 thr, 2 CTA/SM =================
// smem: Q 16KB | K 32KB | V 32KB | lsum 512B.  O-reduction reuses K (32KB).
#define F2_Q 0
#define F2_K 16384
#define F2_V (16384 + 32768)
#define F2_L (F2_V + 32768)
#define F2_TOT (F2_L + 512 + 128)

// K or V^T tile: 128 rows x 128 halves, 2 sub-tiles of 16KB, 256 threads
__device__ __forceinline__ void fl_load128(
    uint32_t sdst, const __half* src, long long ld, int tid)
{
#pragma unroll
    for (int i = 0; i < 8; i++) {
        int li = tid + 256 * i;
        int row = li >> 4, cc = li & 15;
        uint32_t dst = sdst + (cc >> 3) * 16384 + row * 128 + (((cc & 7) ^ (row & 7)) * 16);
        cp16(dst, src + (long long)row * ld + cc * 8);
    }
}

__global__ __launch_bounds__(256, 2) void flash_kernel()
{
    int b = blockIdx.x;
    int bm = 31 - (b >> 5);     // q-block of 64 rows; heavy first
    int h  = b & 31;
    int kvh = h >> 3;

    extern __shared__ char sm[];
    uint32_t sbase = smem_u32(sm);
    float* lsum = (float*)(sm + F2_L);

    int tid = threadIdx.x;
    int w = tid >> 5, lane = tid & 31;
    int wm = w & 3, wn = w >> 2;
    int r = lane >> 2, c = lane & 3;

    int am  = wm * 16 + ((lane >> 3) & 1) * 8 + (lane & 7);
    int am7 = am & 7;
    int ahi = lane >> 4;
    uint32_t aoff = (uint32_t)am * 128u;
    int bro = ((lane >> 4) << 3) + (lane & 7);
    int bcb = (lane >> 3) & 1;
    int bb7 = bro & 7;

    const __half* qsrc = g_q + ((size_t)h * TT + (size_t)bm * 64) * HD;
    const __half* ksrc = g_k + (size_t)kvh * TT * HD;
    const __half* vsrc = g_vt + (size_t)kvh * HD * TT;

    // prologue: Q (64x128) + K(0) + V(0)
#pragma unroll
    for (int i = 0; i < 4; i++) {
        int li = tid + 256 * i;
        int row = li >> 4, cc = li & 15;   // row 0..63
        uint32_t dst = sbase + F2_Q + (cc >> 3) * 8192 + row * 128 + (((cc & 7) ^ (row & 7)) * 16);
        cp16(dst, qsrc + (long long)row * HD + cc * 8);
    }
    fl_load128(sbase + F2_K, ksrc, HD, tid);
#pragma unroll
    for (int i = 0; i < 8; i++) {
        int li = tid + 256 * i;
        int row = li >> 4, cc = li & 15;
        uint32_t dst = sbase + F2_V + (cc >> 3) * 16384 + row * 128 + (((cc & 7) ^ (row & 7)) * 16);
        cp16(dst, vsrc + (size_t)row * TT + cc * 8);
    }
    asm volatile("cp.async.commit_group;" ::: "memory");

    float acc_o[16][4];
#pragma unroll
    for (int i = 0; i < 16; i++)
#pragma unroll
        for (int k = 0; k < 4; k++) acc_o[i][k] = 0.f;
    float l0a = 0.f, l0b = 0.f, l1a = 0.f, l1b = 0.f;

    int mrow0 = wm * 16 + r;            // local q row (0..63)
    int nj = (bm >> 1) + 1;

    for (int j = 0; j < nj; j++) {
        if (j > 0) {
            __syncthreads();            // K/V(j-1) fully consumed
            fl_load128(sbase + F2_K, ksrc + (size_t)j * 128 * HD, HD, tid);
#pragma unroll
            for (int i = 0; i < 8; i++) {
                int li = tid + 256 * i;
                int row = li >> 4, cc = li & 15;
                uint32_t dst = sbase + F2_V + (cc >> 3) * 16384 + row * 128
                             + (((cc & 7) ^ (row & 7)) * 16);
                cp16(dst, vsrc + (size_t)row * TT + j * 128 + cc * 8);
            }
            asm volatile("cp.async.commit_group;" ::: "memory");
        }
        asm volatile("cp.async.wait_group 0;" ::: "memory");
        __syncthreads();

        // ---- S = Q @ K^T (Q pre-scaled by d^-1/2 * log2e) ----
        float acc_s[8][4];
#pragma unroll
        for (int i = 0; i < 8; i++)
#pragma unroll
            for (int k = 0; k < 4; k++) acc_s[i][k] = 0.f;

        uint32_t squ = sbase + F2_Q;
        uint32_t sku = sbase + F2_K;
#pragma unroll
        for (int kt = 0; kt < 2; kt++) {
#pragma unroll
            for (int ks = 0; ks < 4; ks++) {
                unsigned a[4];
                ldsm4(a, squ + kt * 8192 + aoff + ((unsigned)((2 * ks + ahi) ^ am7) << 4));
#pragma unroll
                for (int ntp = 0; ntp < 4; ntp++) {
                    unsigned bb[4];
                    ldsm4(bb, sku + kt * 16384 + (unsigned)(wn * 64 + ntp * 16 + bro) * 128
                              + ((unsigned)((2 * ks + bcb) ^ bb7) << 4));
                    mma_f16(acc_s[2 * ntp],     a, bb);
                    mma_f16(acc_s[2 * ntp + 1], a, bb + 2);
                }
            }
        }

        // ---- interleaved exp2/mask/pack + PV mma (per ks-chunk) ----
        bool diag = (j == nj - 1);
        int lim = bm * 64 + mrow0 - j * 128;   // causal limit (local kv index)
        uint32_t svu = sbase + F2_V + wn * 16384;
#pragma unroll
        for (int ks = 0; ks < 4; ks++) {
            unsigned a[4];
#pragma unroll
            for (int q = 0; q < 2; q++) {
                int nt = 2 * ks + q;
                int n0 = wn * 64 + nt * 8 + 2 * c;
                float v0 = ex2f(acc_s[nt][0] - EXP_SHIFT_L2);
                float v1 = ex2f(acc_s[nt][1] - EXP_SHIFT_L2);
                float v2 = ex2f(acc_s[nt][2] - EXP_SHIFT_L2);
                float v3 = ex2f(acc_s[nt][3] - EXP_SHIFT_L2);
                if (diag) {
                    if (n0     > lim)     v0 = 0.f;
                    if (n0 + 1 > lim)     v1 = 0.f;
                    if (n0     > lim + 8) v2 = 0.f;
                    if (n0 + 1 > lim + 8) v3 = 0.f;
                }
                if (q == 0) { l0a += v0 + v1; l1a += v2 + v3; }
                else        { l0b += v0 + v1; l1b += v2 + v3; }
                __half2 h01 = __floats2half2_rn(v0, v1);
                __half2 h23 = __floats2half2_rn(v2, v3);
                a[2 * q]     = *(unsigned*)&h01;
                a[2 * q + 1] = *(unsigned*)&h23;
            }
#pragma unroll
            for (int dnp = 0; dnp < 8; dnp++) {
                unsigned bb[4];
                ldsm4(bb, svu + (unsigned)(dnp * 16 + bro) * 128
                          + ((unsigned)((2 * ks + bcb) ^ bb7) << 4));
                mma_f16(acc_o[2 * dnp],     a, bb);
                mma_f16(acc_o[2 * dnp + 1], a, bb + 2);
            }
        }
    }

    // ---- cross-slice reduction + normalize + write ----
    __syncthreads();
    float* red = (float*)(sm + F2_K);   // 32KB, K buffer retired

    if (wn == 1) {
        float* dst = red + wm * 2048;   // 16 rows x 128 floats
#pragma unroll
        for (int dn = 0; dn < 16; dn++) {
            *(float2*)(dst + r * 128 + dn * 8 + 2 * c)       = make_float2(acc_o[dn][0], acc_o[dn][1]);
            *(float2*)(dst + (r + 8) * 128 + dn * 8 + 2 * c) = make_float2(acc_o[dn][2], acc_o[dn][3]);
        }
    }
    float l0 = l0a + l0b, l1 = l1a + l1b;
    l0 += __shfl_xor_sync(0xffffffffu, l0, 1);
    l0 += __shfl_xor_sync(0xffffffffu, l0, 2);
    l1 += __shfl_xor_sync(0xffffffffu, l1, 1);
    l1 += __shfl_xor_sync(0xffffffffu, l1, 2);
    if (c == 0) {
        lsum[wn * 64 + wm * 16 + r]     = l0;
        lsum[wn * 64 + wm * 16 + r + 8] = l1;
    }
    __syncthreads();

    if (wn == 0) {
        int row0 = wm * 16 + r;
        float inv0 = 1.f / (lsum[row0]     + lsum[64 + row0]);
        float inv1 = 1.f / (lsum[row0 + 8] + lsum[64 + row0 + 8]);
        const float* src = red + wm * 2048;
        __half* o0 = g_attn + (size_t)(bm * 64 + row0) * QS + h * 128;
        __half* o1 = g_attn + (size_t)(bm * 64 + row0 + 8) * QS + h * 128;
#pragma unroll
        for (int dn = 0; dn < 16; dn++) {
            int nc = dn * 8 + 2 * c;
            float2 s0 = *(const float2*)(src + r * 128 + nc);
            float2 s1 = *(const float2*)(src + (r + 8) * 128 + nc);
            *(__half2*)(o0 + nc) = __floats2half2_rn((acc_o[dn][0] + s0.x) * inv0,
                                                     (acc_o[dn][1] + s0.y) * inv0);
            *(__half2*)(o1 + nc) = __floats2half2_rn((acc_o[dn][2] + s1.x) * inv1,
                                                     (acc_o[dn][3] + s1.y) * inv1);
        }
    }
}

// ---------------- fp32 -> fp16 conversion (all three arrays + invf, one launch) ----------------
#define N4_HID  (TT * HIDDEN / 4)
#define N4_WQKV (QKVN * HIDDEN / 4)
#define N4_WO   (HIDDEN * QS / 4)
__global__ void h_conv_all(const float4* __restrict__ s0, uint2* __restrict__ d0,
                           const float4* __restrict__ s1, uint2* __restrict__ d1,
                           const float4* __restrict__ s2, uint2* __restrict__ d2) {
    if (blockIdx.x == 0 && threadIdx.x < 64)
        g_invf[threadIdx.x] = (float)exp(-(double)threadIdx.x * (log(10000.0) / 64.0));
    int i = blockIdx.x * 256 + threadIdx.x;
    int stride = gridDim.x * 256;
    int ntot = N4_HID + N4_WQKV + N4_WO;
    for (; i < ntot; i += stride) {
        const float4* s; uint2* d; int idx;
        if (i < N4_HID)              { s = s0; d = d0; idx = i; }
        else if (i < N4_HID + N4_WQKV) { s = s1; d = d1; idx = i - N4_HID; }
        else                         { s = s2; d = d2; idx = i - N4_HID - N4_WQKV; }
        float4 v = s[idx];
        __half2 lo = __floats2half2_rn(v.x, v.y);
        __half2 hi = __floats2half2_rn(v.z, v.w);
        uint2 o;
        o.x = *(unsigned*)&lo;
        o.y = *(unsigned*)&hi;
        d[idx] = o;
    }
}

// ---------------- launcher ----------------
extern "C" void kernel_launch(void* const* d_in, const int* in_sizes, int n_in,
                              void* d_out, int out_size)
{
    const int* positions = (const int*)d_in[0];   // int32 (JAX x64 disabled)
    const float* hidden = (const float*)d_in[1];
    const float* w_qkv  = (const float*)d_in[2];
    const float* w_o    = (const float*)d_in[3];
    const float* qw     = (const float*)d_in[4];
    const float* kw     = (const float*)d_in[5];
    float* out = (float*)d_out;

    __half *p_attn, *p_hidh, *p_wqkvh, *p_woh;
    cudaGetSymbolAddress((void**)&p_attn,  g_attn);
    cudaGetSymbolAddress((void**)&p_hidh,  g_hidh);
    cudaGetSymbolAddress((void**)&p_wqkvh, g_wqkvh);
    cudaGetSymbolAddress((void**)&p_woh,   g_woh);

    cudaFuncSetAttribute(gemm_h, cudaFuncAttributeMaxDynamicSharedMemorySize, SM_TOT);
    cudaFuncSetAttribute(flash_kernel, cudaFuncAttributeMaxDynamicSharedMemorySize, F2_TOT);

    // 0) fp16 conversions + invf (one launch)
    h_conv_all<<<2048, 256>>>((const float4*)hidden, (uint2*)p_hidh,
                              (const float4*)w_qkv,  (uint2*)p_wqkvh,
                              (const float4*)w_o,    (uint2*)p_woh);

    // 1) QKV projection with fused RMSNorm+RoPE+reorder epilogue
    gemm_h<<<dim3(QKVN / BN, TT / BM, 1), 256, SM_TOT>>>(
        p_hidh, p_wqkvh, nullptr, HIDDEN, HIDDEN, HIDDEN, 0, 1.0f,
        positions, qw, kw, 1);

    // 2) fused flash attention (64-row q-tiles, 2 CTA/SM) -> g_attn (fp16)
    flash_kernel<<<1024, 256, F2_TOT>>>();

    // 3) output projection (fp32 out)
    gemm_h<<<dim3(HIDDEN / BN, TT / BM, 1), 256, SM_TOT>>>(
        p_attn, p_woh, out, QS, QS, QS, HIDDEN, 1.0f,
        nullptr, nullptr, nullptr, 0);
}

// round 14
// speedup vs baseline: 1.0680x; 1.0078x over previous
#include <cuda_runtime.h>
#include <cuda_fp16.h>
#include <math.h>
#include <float.h>
#include <stdint.h>

#define TT 2048
#define HIDDEN 2048
#define NH 32
#define NKV 4
#define HD 128
#define QS (NH*HD)        // 4096
#define KVS (NKV*HD)      // 512
#define QKVN (QS + 2*KVS) // 5120

// ---------------- scratch (static device globals; no allocs) ----------------
__device__ __half g_q   [(size_t)NH * TT * HD];   //  16 MB [h][t][d]  (pre-scaled by d^-1/2 * log2e)
__device__ __half g_k   [(size_t)NKV * TT * HD];  //   2 MB [kv][t][d]
__device__ __half g_vt  [(size_t)NKV * HD * TT];  //   2 MB [kv][d][t]
__device__ __half g_attn[(size_t)TT * QS];        //  16 MB [t][h*128+d]
__device__ __half g_hidh [(size_t)TT * HIDDEN];   //   8 MB fp16(hidden)
__device__ __half g_wqkvh[(size_t)QKVN * HIDDEN]; //  20 MB fp16(w_qkv)
__device__ __half g_woh  [(size_t)HIDDEN * QS];   //  16 MB fp16(w_o)
__device__ float  g_invf[64];

#define ATT_SCALE 0.08838834764831845f
#define LOG2E 1.4426950408889634f
#define EXP_SHIFT_L2 5.7707801635558535f   // 4 * log2(e)

// ---------------- helpers ----------------
__device__ __forceinline__ uint32_t smem_u32(const void* p) {
    uint32_t a;
    asm("{ .reg .u64 t; cvta.to.shared.u64 t, %1; cvt.u32.u64 %0, t; }" : "=r"(a) : "l"(p));
    return a;
}
__device__ __forceinline__ void cp16(uint32_t dst, const void* src) {
    asm volatile("cp.async.cg.shared.global [%0], [%1], 16;" :: "r"(dst), "l"(src));
}
__device__ __forceinline__ void mma_f16(float* d, const unsigned* a, const unsigned* b) {
    asm volatile(
        "mma.sync.aligned.m16n8k16.row.col.f32.f16.f16.f32 "
        "{%0,%1,%2,%3}, {%4,%5,%6,%7}, {%8,%9}, {%0,%1,%2,%3};\n"
        : "+f"(d[0]), "+f"(d[1]), "+f"(d[2]), "+f"(d[3])
        : "r"(a[0]), "r"(a[1]), "r"(a[2]), "r"(a[3]), "r"(b[0]), "r"(b[1]));
}
__device__ __forceinline__ void ldsm4(unsigned* r, uint32_t addr) {
    asm volatile("ldmatrix.sync.aligned.m8n8.x4.shared.b16 {%0,%1,%2,%3}, [%4];"
        : "=r"(r[0]), "=r"(r[1]), "=r"(r[2]), "=r"(r[3]) : "r"(addr));
}
__device__ __forceinline__ float ex2f(float x) {
    float y;
    asm("ex2.approx.f32 %0, %1;" : "=f"(y) : "f"(x));
    return y;
}

// ================= dense fp16 TN GEMM (128x128, 256 thr, 2 CTA/SM) =================
#define STAGES 3
#define TILE_BYTES 16384
#define STAGE_BYTES 32768
#define SM_TOT (STAGES*STAGE_BYTES + 512)
#define BM 128
#define BN 128

// mode 0: plain fp32 C out
// mode 1: fused QKV epilogue: bn = head (0-31 q, 32-35 k, 36-39 v)
__global__ __launch_bounds__(256, 2) void gemm_h(
    const __half* __restrict__ A, const __half* __restrict__ B, float* __restrict__ C,
    int K, int lda, int ldb, int ldc, float scale,
    const int* __restrict__ positions, const float* __restrict__ qw,
    const float* __restrict__ kw, int mode)
{
    int bm = blockIdx.y, bn = blockIdx.x;

    extern __shared__ char smem[];
    uint32_t sbase = smem_u32(smem);

    int tid  = threadIdx.x;
    int warp = tid >> 5, lane = tid & 31;
    int wm = warp & 3, wn = warp >> 2;
    int r = lane >> 2, c = lane & 3;

    int arow_in = ((lane >> 3) & 1) * 8 + (lane & 7);
    int ahi = lane >> 4;
    int am7 = lane & 7;
    int bro = ((lane >> 4) << 3) + (lane & 7);
    int bcb = (lane >> 3) & 1;
    int bb7 = lane & 7;

    float acc[2][8][4];
#pragma unroll
    for (int i = 0; i < 2; i++)
#pragma unroll
        for (int j = 0; j < 8; j++)
#pragma unroll
            for (int k = 0; k < 4; k++) acc[i][j][k] = 0.f;

    int nkt = K >> 6;
    const __half* Ab = A + (long long)bm * BM * lda;
    const __half* Bb = B + (long long)bn * BN * ldb;

    int sm_ = tid >> 1;
    int scb = (tid & 1) * 4;
    long long arow = (long long)sm_ * lda;
    long long brow = (long long)sm_ * ldb;

#pragma unroll
    for (int p = 0; p < STAGES - 1; p++) {
        if (p < nkt) {
            int kb = p << 6;
            uint32_t aD = sbase + p * STAGE_BYTES + sm_ * 128;
            uint32_t bD = aD + TILE_BYTES;
            const __half* as = Ab + arow + kb + scb * 8;
            const __half* bs = Bb + brow + kb + scb * 8;
#pragma unroll
            for (int j = 0; j < 4; j++) {
                int sw = ((scb + j) ^ (sm_ & 7)) * 16;
                cp16(aD + sw, as + j * 8);
                cp16(bD + sw, bs + j * 8);
            }
        }
        asm volatile("cp.async.commit_group;" ::: "memory");
    }

    for (int kt = 0; kt < nkt; kt++) {
        asm volatile("cp.async.wait_group 1;" ::: "memory");
        __syncthreads();

        if (kt + STAGES - 1 < nkt) {
            int kn = kt + STAGES - 1;
            int kb = kn << 6;
            uint32_t aD = sbase + (kn % STAGES) * STAGE_BYTES + sm_ * 128;
            uint32_t bD = aD + TILE_BYTES;
            const __half* as = Ab + arow + kb + scb * 8;
            const __half* bs = Bb + brow + kb + scb * 8;
#pragma unroll
            for (int j = 0; j < 4; j++) {
                int sw = ((scb + j) ^ (sm_ & 7)) * 16;
                cp16(aD + sw, as + j * 8);
                cp16(bD + sw, bs + j * 8);
            }
        }
        asm volatile("cp.async.commit_group;" ::: "memory");

        uint32_t sa  = sbase + (kt % STAGES) * STAGE_BYTES;
        uint32_t sbm = sa + TILE_BYTES;

#pragma unroll
        for (int ks = 0; ks < 4; ks++) {
            unsigned a[2][4];
#pragma unroll
            for (int mt = 0; mt < 2; mt++) {
                uint32_t row = (uint32_t)(wm * 32 + mt * 16 + arow_in);
                ldsm4(a[mt], sa + row * 128u + ((unsigned)((2 * ks + ahi) ^ am7) << 4));
            }
#pragma unroll
            for (int ntp = 0; ntp < 4; ntp++) {
                unsigned bb[4];
                uint32_t row = (uint32_t)(wn * 64 + ntp * 16 + bro);
                ldsm4(bb, sbm + row * 128u + ((unsigned)((2 * ks + bcb) ^ bb7) << 4));
#pragma unroll
                for (int mt = 0; mt < 2; mt++) {
                    mma_f16(acc[mt][2 * ntp],     a[mt], bb);
                    mma_f16(acc[mt][2 * ntp + 1], a[mt], bb + 2);
                }
            }
        }
    }

    asm volatile("cp.async.wait_group 0;" ::: "memory");

    if (mode == 0) {
#pragma unroll
        for (int mt = 0; mt < 2; mt++) {
            int m0 = bm * BM + wm * 32 + mt * 16 + r;
#pragma unroll
            for (int nt = 0; nt < 8; nt++) {
                int n0 = bn * BN + wn * 64 + nt * 8 + 2 * c;
                *(float2*)(C + (long long)m0 * ldc + n0) =
                    make_float2(acc[mt][nt][0] * scale, acc[mt][nt][1] * scale);
                *(float2*)(C + (long long)(m0 + 8) * ldc + n0) =
                    make_float2(acc[mt][nt][2] * scale, acc[mt][nt][3] * scale);
            }
        }
        return;
    }

    // ---- fused QKV epilogue: acc -> smem buf (128 x 132 fp32), then norm/rope/transpose ----
    __syncthreads();
    float* buf = (float*)smem;
#pragma unroll
    for (int mt = 0; mt < 2; mt++) {
        int mrow = wm * 32 + mt * 16 + r;
#pragma unroll
        for (int nt = 0; nt < 8; nt++) {
            int nc = wn * 64 + nt * 8 + 2 * c;
            *(float2*)(buf + mrow * 132 + nc)       = make_float2(acc[mt][nt][0], acc[mt][nt][1]);
            *(float2*)(buf + (mrow + 8) * 132 + nc) = make_float2(acc[mt][nt][2], acc[mt][nt][3]);
        }
    }
    __syncthreads();

    int h = bn;
    if (h < 36) {
        int row = tid >> 1, half = tid & 1;
        int t = bm * BM + row;
        const float* own = buf + row * 132 + half * 64;
        const float* par = buf + row * 132 + (half ^ 1) * 64;

        float ss = 0.f;
#pragma unroll
        for (int i = 0; i < 16; i++) {
            float4 v = *(const float4*)(own + i * 4);
            ss += v.x * v.x + v.y * v.y + v.z * v.z + v.w * v.w;
        }
        ss += __shfl_xor_sync(0xffffffffu, ss, 1);
        float rinv = rsqrtf(ss * (1.f / 128.f) + 1e-6f);

        const float* w_ = (h < 32) ? qw : kw;
        float pos = (float)positions[t];
        float osc = (h < 32) ? (ATT_SCALE * LOG2E) : 1.f;
        float sgn = half ? 1.f : -1.f;
        __half* outp;
        if (h < 32) outp = g_q + ((size_t)h * TT + t) * HD + half * 64;
        else        outp = g_k + ((size_t)(h - 32) * TT + t) * HD + half * 64;

#pragma unroll 8
        for (int i = 0; i < 64; i += 2) {
            float cs0 = 0.f, sn0 = 0.f, cs1 = 0.f, sn1 = 0.f;
            if (!(lane & 1)) {
                float a0 = pos * g_invf[i], a1 = pos * g_invf[i + 1];
                cs0 = cosf(a0); sn0 = sinf(a0);
                cs1 = cosf(a1); sn1 = sinf(a1);
            }
            cs0 = __shfl_sync(0xffffffffu, cs0, lane & ~1);
            sn0 = __shfl_sync(0xffffffffu, sn0, lane & ~1);
            cs1 = __shfl_sync(0xffffffffu, cs1, lane & ~1);
            sn1 = __shfl_sync(0xffffffffu, sn1, lane & ~1);
            float y0 = own[i]     * rinv * w_[half * 64 + i];
            float y1 = own[i + 1] * rinv * w_[half * 64 + i + 1];
            float z0 = par[i]     * rinv * w_[(half ^ 1) * 64 + i];
            float z1 = par[i + 1] * rinv * w_[(half ^ 1) * 64 + i + 1];
            float o0 = (y0 * cs0 + sgn * z0 * sn0) * osc;
            float o1 = (y1 * cs1 + sgn * z1 * sn1) * osc;
            *(__half2*)(outp + i) = __floats2half2_rn(o0, o1);
        }
    } else {
        int d = tid >> 1, thalf = tid & 1;
        int kvh = h - 36;
        __half* vp = g_vt + ((size_t)kvh * HD + d) * TT + (size_t)bm * BM + thalf * 64;
#pragma unroll 8
        for (int j2 = 0; j2 < 64; j2 += 2) {
            float v0 = buf[(thalf * 64 + j2) * 132 + d];
            float v1 = buf[(thalf * 64 + j2 + 1) * 132 + d];
            *(__half2*)(vp + j2) = __floats2half2_rn(v0, v1);
        }
    }
}

// ================= fused flash attention: q64, 256 thr, 2 CTA/SM, K double-buffered =================
// smem: Q 16KB | K0 32KB | K1 32KB | V 32KB | lsum 512B.  O-reduction reuses K0 (32KB).
#define F3_Q  0
#define F3_K0 16384
#define F3_K1 49152
#define F3_V  81920
#define F3_L  114688
#define F3_TOT (F3_L + 512 + 128)

// K tile: 128 rows x 128 halves, 2 sub-tiles of 16KB, 256 threads
__device__ __forceinline__ void fl_load128(
    uint32_t sdst, const __half* src, long long ld, int tid)
{
#pragma unroll
    for (int i = 0; i < 8; i++) {
        int li = tid + 256 * i;
        int row = li >> 4, cc = li & 15;
        uint32_t dst = sdst + (cc >> 3) * 16384 + row * 128 + (((cc & 7) ^ (row & 7)) * 16);
        cp16(dst, src + (long long)row * ld + cc * 8);
    }
}

__global__ __launch_bounds__(256, 2) void flash_kernel()
{
    int b = blockIdx.x;
    int bm = 31 - (b >> 5);     // q-block of 64 rows; heavy first
    int h  = b & 31;
    int kvh = h >> 3;

    extern __shared__ char sm[];
    uint32_t sbase = smem_u32(sm);
    float* lsum = (float*)(sm + F3_L);

    int tid = threadIdx.x;
    int w = tid >> 5, lane = tid & 31;
    int wm = w & 3, wn = w >> 2;
    int r = lane >> 2, c = lane & 3;

    int am  = wm * 16 + ((lane >> 3) & 1) * 8 + (lane & 7);
    int am7 = am & 7;
    int ahi = lane >> 4;
    uint32_t aoff = (uint32_t)am * 128u;
    int bro = ((lane >> 4) << 3) + (lane & 7);
    int bcb = (lane >> 3) & 1;
    int bb7 = bro & 7;

    const __half* qsrc = g_q + ((size_t)h * TT + (size_t)bm * 64) * HD;
    const __half* ksrc = g_k + (size_t)kvh * TT * HD;
    const __half* vsrc = g_vt + (size_t)kvh * HD * TT;

    int nj = (bm >> 1) + 1;

    // prologue: G0 = Q(64x128) + K(0) + V(0); G1 = K(1)
#pragma unroll
    for (int i = 0; i < 4; i++) {
        int li = tid + 256 * i;
        int row = li >> 4, cc = li & 15;   // row 0..63
        uint32_t dst = sbase + F3_Q + (cc >> 3) * 8192 + row * 128 + (((cc & 7) ^ (row & 7)) * 16);
        cp16(dst, qsrc + (long long)row * HD + cc * 8);
    }
    fl_load128(sbase + F3_K0, ksrc, HD, tid);
#pragma unroll
    for (int i = 0; i < 8; i++) {
        int li = tid + 256 * i;
        int row = li >> 4, cc = li & 15;
        uint32_t dst = sbase + F3_V + (cc >> 3) * 16384 + row * 128 + (((cc & 7) ^ (row & 7)) * 16);
        cp16(dst, vsrc + (size_t)row * TT + cc * 8);
    }
    asm volatile("cp.async.commit_group;" ::: "memory");
    if (nj > 1)
        fl_load128(sbase + F3_K1, ksrc + (size_t)128 * HD, HD, tid);
    asm volatile("cp.async.commit_group;" ::: "memory");

    float acc_o[16][4];
#pragma unroll
    for (int i = 0; i < 16; i++)
#pragma unroll
        for (int k = 0; k < 4; k++) acc_o[i][k] = 0.f;
    float l0a = 0.f, l0b = 0.f, l1a = 0.f, l1b = 0.f;

    int mrow0 = wm * 16 + r;            // local q row (0..63)

    for (int j = 0; j < nj; j++) {
        uint32_t kbuf = sbase + ((j & 1) ? F3_K1 : F3_K0);

        if (j > 0) {
            __syncthreads();            // PV(j-1) done (V buf free), K(j-1) buf free
            // V(j) into single V buffer (lands under S phase)
#pragma unroll
            for (int i = 0; i < 8; i++) {
                int li = tid + 256 * i;
                int row = li >> 4, cc = li & 15;
                uint32_t dst = sbase + F3_V + (cc >> 3) * 16384 + row * 128
                             + (((cc & 7) ^ (row & 7)) * 16);
                cp16(dst, vsrc + (size_t)row * TT + j * 128 + cc * 8);
            }
            asm volatile("cp.async.commit_group;" ::: "memory");   // group V_j
            // K(j+1) into alternate buffer (lands under full iteration)
            if (j + 1 < nj)
                fl_load128(sbase + (((j + 1) & 1) ? F3_K1 : F3_K0),
                           ksrc + (size_t)(j + 1) * 128 * HD, HD, tid);
            asm volatile("cp.async.commit_group;" ::: "memory");   // group K_{j+1}
            asm volatile("cp.async.wait_group 2;" ::: "memory");   // K(j) complete
            __syncthreads();
        } else {
            asm volatile("cp.async.wait_group 1;" ::: "memory");   // G0: Q,K0,V0
            __syncthreads();
        }

        // ---- S = Q @ K^T (Q pre-scaled by d^-1/2 * log2e) ----
        float acc_s[8][4];
#pragma unroll
        for (int i = 0; i < 8; i++)
#pragma unroll
            for (int k = 0; k < 4; k++) acc_s[i][k] = 0.f;

        uint32_t squ = sbase + F3_Q;
#pragma unroll
        for (int kt = 0; kt < 2; kt++) {
#pragma unroll
            for (int ks = 0; ks < 4; ks++) {
                unsigned a[4];
                ldsm4(a, squ + kt * 8192 + aoff + ((unsigned)((2 * ks + ahi) ^ am7) << 4));
#pragma unroll
                for (int ntp = 0; ntp < 4; ntp++) {
                    unsigned bb[4];
                    ldsm4(bb, kbuf + kt * 16384 + (unsigned)(wn * 64 + ntp * 16 + bro) * 128
                              + ((unsigned)((2 * ks + bcb) ^ bb7) << 4));
                    mma_f16(acc_s[2 * ntp],     a, bb);
                    mma_f16(acc_s[2 * ntp + 1], a, bb + 2);
                }
            }
        }

        if (j > 0) {
            asm volatile("cp.async.wait_group 1;" ::: "memory");   // V(j) complete
            __syncthreads();
        }

        // ---- interleaved exp2/mask/pack + PV mma (per ks-chunk) ----
        bool diag = (j == nj - 1);
        int lim = bm * 64 + mrow0 - j * 128;   // causal limit (local kv index)
        uint32_t svu = sbase + F3_V + wn * 16384;
#pragma unroll
        for (int ks = 0; ks < 4; ks++) {
            unsigned a[4];
#pragma unroll
            for (int q = 0; q < 2; q++) {
                int nt = 2 * ks + q;
                int n0 = wn * 64 + nt * 8 + 2 * c;
                float v0 = ex2f(acc_s[nt][0] - EXP_SHIFT_L2);
                float v1 = ex2f(acc_s[nt][1] - EXP_SHIFT_L2);
                float v2 = ex2f(acc_s[nt][2] - EXP_SHIFT_L2);
                float v3 = ex2f(acc_s[nt][3] - EXP_SHIFT_L2);
                if (diag) {
                    if (n0     > lim)     v0 = 0.f;
                    if (n0 + 1 > lim)     v1 = 0.f;
                    if (n0     > lim + 8) v2 = 0.f;
                    if (n0 + 1 > lim + 8) v3 = 0.f;
                }
                if (q == 0) { l0a += v0 + v1; l1a += v2 + v3; }
                else        { l0b += v0 + v1; l1b += v2 + v3; }
                __half2 h01 = __floats2half2_rn(v0, v1);
                __half2 h23 = __floats2half2_rn(v2, v3);
                a[2 * q]     = *(unsigned*)&h01;
                a[2 * q + 1] = *(unsigned*)&h23;
            }
#pragma unroll
            for (int dnp = 0; dnp < 8; dnp++) {
                unsigned bb[4];
                ldsm4(bb, svu + (unsigned)(dnp * 16 + bro) * 128
                          + ((unsigned)((2 * ks + bcb) ^ bb7) << 4));
                mma_f16(acc_o[2 * dnp],     a, bb);
                mma_f16(acc_o[2 * dnp + 1], a, bb + 2);
            }
        }
    }

    asm volatile("cp.async.wait_group 0;" ::: "memory");

    // ---- cross-slice reduction + normalize + write ----
    __syncthreads();
    float* red = (float*)(sm + F3_K0);   // 32KB, K0 buffer retired

    if (wn == 1) {
        float* dst = red + wm * 2048;    // 16 rows x 128 floats
#pragma unroll
        for (int dn = 0; dn < 16; dn++) {
            *(float2*)(dst + r * 128 + dn * 8 + 2 * c)       = make_float2(acc_o[dn][0], acc_o[dn][1]);
            *(float2*)(dst + (r + 8) * 128 + dn * 8 + 2 * c) = make_float2(acc_o[dn][2], acc_o[dn][3]);
        }
    }
    float l0 = l0a + l0b, l1 = l1a + l1b;
    l0 += __shfl_xor_sync(0xffffffffu, l0, 1);
    l0 += __shfl_xor_sync(0xffffffffu, l0, 2);
    l1 += __shfl_xor_sync(0xffffffffu, l1, 1);
    l1 += __shfl_xor_sync(0xffffffffu, l1, 2);
    if (c == 0) {
        lsum[wn * 64 + wm * 16 + r]     = l0;
        lsum[wn * 64 + wm * 16 + r + 8] = l1;
    }
    __syncthreads();

    if (wn == 0) {
        int row0 = wm * 16 + r;
        float inv0 = 1.f / (lsum[row0]     + lsum[64 + row0]);
        float inv1 = 1.f / (lsum[row0 + 8] + lsum[64 + row0 + 8]);
        const float* src = red + wm * 2048;
        __half* o0 = g_attn + (size_t)(bm * 64 + row0) * QS + h * 128;
        __half* o1 = g_attn + (size_t)(bm * 64 + row0 + 8) * QS + h * 128;
#pragma unroll
        for (int dn = 0; dn < 16; dn++) {
            int nc = dn * 8 + 2 * c;
            float2 s0 = *(const float2*)(src + r * 128 + nc);
            float2 s1 = *(const float2*)(src + (r + 8) * 128 + nc);
            *(__half2*)(o0 + nc) = __floats2half2_rn((acc_o[dn][0] + s0.x) * inv0,
                                                     (acc_o[dn][1] + s0.y) * inv0);
            *(__half2*)(o1 + nc) = __floats2half2_rn((acc_o[dn][2] + s1.x) * inv1,
                                                     (acc_o[dn][3] + s1.y) * inv1);
        }
    }
}

// ---------------- fp32 -> fp16 conversion (all three arrays + invf, one launch) ----------------
#define N4_HID  (TT * HIDDEN / 4)
#define N4_WQKV (QKVN * HIDDEN / 4)
#define N4_WO   (HIDDEN * QS / 4)
__global__ void h_conv_all(const float4* __restrict__ s0, uint2* __restrict__ d0,
                           const float4* __restrict__ s1, uint2* __restrict__ d1,
                           const float4* __restrict__ s2, uint2* __restrict__ d2) {
    if (blockIdx.x == 0 && threadIdx.x < 64)
        g_invf[threadIdx.x] = (float)exp(-(double)threadIdx.x * (log(10000.0) / 64.0));
    int i = blockIdx.x * 256 + threadIdx.x;
    int stride = gridDim.x * 256;
    int ntot = N4_HID + N4_WQKV + N4_WO;
    for (; i < ntot; i += stride) {
        const float4* s; uint2* d; int idx;
        if (i < N4_HID)              { s = s0; d = d0; idx = i; }
        else if (i < N4_HID + N4_WQKV) { s = s1; d = d1; idx = i - N4_HID; }
        else                         { s = s2; d = d2; idx = i - N4_HID - N4_WQKV; }
        float4 v = s[idx];
        __half2 lo = __floats2half2_rn(v.x, v.y);
        __half2 hi = __floats2half2_rn(v.z, v.w);
        uint2 o;
        o.x = *(unsigned*)&lo;
        o.y = *(unsigned*)&hi;
        d[idx] = o;
    }
}

// ---------------- launcher ----------------
extern "C" void kernel_launch(void* const* d_in, const int* in_sizes, int n_in,
                              void* d_out, int out_size)
{
    const int* positions = (const int*)d_in[0];   // int32 (JAX x64 disabled)
    const float* hidden = (const float*)d_in[1];
    const float* w_qkv  = (const float*)d_in[2];
    const float* w_o    = (const float*)d_in[3];
    const float* qw     = (const float*)d_in[4];
    const float* kw     = (const float*)d_in[5];
    float* out = (float*)d_out;

    __half *p_attn, *p_hidh, *p_wqkvh, *p_woh;
    cudaGetSymbolAddress((void**)&p_attn,  g_attn);
    cudaGetSymbolAddress((void**)&p_hidh,  g_hidh);
    cudaGetSymbolAddress((void**)&p_wqkvh, g_wqkvh);
    cudaGetSymbolAddress((void**)&p_woh,   g_woh);

    cudaFuncSetAttribute(gemm_h, cudaFuncAttributeMaxDynamicSharedMemorySize, SM_TOT);
    cudaFuncSetAttribute(flash_kernel, cudaFuncAttributeMaxDynamicSharedMemorySize, F3_TOT);

    // 0) fp16 conversions + invf (one launch)
    h_conv_all<<<2048, 256>>>((const float4*)hidden, (uint2*)p_hidh,
                              (const float4*)w_qkv,  (uint2*)p_wqkvh,
                              (const float4*)w_o,    (uint2*)p_woh);

    // 1) QKV projection with fused RMSNorm+RoPE+reorder epilogue
    gemm_h<<<dim3(QKVN / BN, TT / BM, 1), 256, SM_TOT>>>(
        p_hidh, p_wqkvh, nullptr, HIDDEN, HIDDEN, HIDDEN, 0, 1.0f,
        positions, qw, kw, 1);

    // 2) fused flash attention (64-row q-tiles, 2 CTA/SM, pipelined K/V) -> g_attn
    flash_kernel<<<1024, 256, F3_TOT>>>();

    // 3) output projection (fp32 out)
    gemm_h<<<dim3(HIDDEN / BN, TT / BM, 1), 256, SM_TOT>>>(
        p_attn, p_woh, out, QS, QS, QS, HIDDEN, 1.0f,
        nullptr, nullptr, nullptr, 0);
}

// round 15
// speedup vs baseline: 1.0832x; 1.0142x over previous
#include <cuda_runtime.h>
#include <cuda_fp16.h>
#include <math.h>
#include <float.h>
#include <stdint.h>

#define TT 2048
#define HIDDEN 2048
#define NH 32
#define NKV 4
#define HD 128
#define QS (NH*HD)        // 4096
#define KVS (NKV*HD)      // 512
#define QKVN (QS + 2*KVS) // 5120

// ---------------- scratch (static device globals; no allocs) ----------------
__device__ __half g_q   [(size_t)NH * TT * HD];   //  16 MB [h][t][d]  (pre-scaled by d^-1/2 * log2e)
__device__ __half g_k   [(size_t)NKV * TT * HD];  //   2 MB [kv][t][d]
__device__ __half g_vt  [(size_t)NKV * HD * TT];  //   2 MB [kv][d][t]
__device__ __half g_attn[(size_t)TT * QS];        //  16 MB [t][h*128+d]
__device__ __half g_hidh [(size_t)TT * HIDDEN];   //   8 MB fp16(hidden)
__device__ __half g_wqkvh[(size_t)QKVN * HIDDEN]; //  20 MB fp16(w_qkv)
__device__ __half g_woh  [(size_t)HIDDEN * QS];   //  16 MB fp16(w_o)
__device__ float  g_invf[64];

#define ATT_SCALE 0.08838834764831845f
#define LOG2E 1.4426950408889634f
#define EXP_SHIFT_L2 5.7707801635558535f   // 4 * log2(e)

// ---------------- helpers ----------------
__device__ __forceinline__ uint32_t smem_u32(const void* p) {
    uint32_t a;
    asm("{ .reg .u64 t; cvta.to.shared.u64 t, %1; cvt.u32.u64 %0, t; }" : "=r"(a) : "l"(p));
    return a;
}
__device__ __forceinline__ void cp16(uint32_t dst, const void* src) {
    asm volatile("cp.async.cg.shared.global [%0], [%1], 16;" :: "r"(dst), "l"(src));
}
__device__ __forceinline__ void mma_f16(float* d, const unsigned* a, const unsigned* b) {
    asm volatile(
        "mma.sync.aligned.m16n8k16.row.col.f32.f16.f16.f32 "
        "{%0,%1,%2,%3}, {%4,%5,%6,%7}, {%8,%9}, {%0,%1,%2,%3};\n"
        : "+f"(d[0]), "+f"(d[1]), "+f"(d[2]), "+f"(d[3])
        : "r"(a[0]), "r"(a[1]), "r"(a[2]), "r"(a[3]), "r"(b[0]), "r"(b[1]));
}
__device__ __forceinline__ void ldsm4(unsigned* r, uint32_t addr) {
    asm volatile("ldmatrix.sync.aligned.m8n8.x4.shared.b16 {%0,%1,%2,%3}, [%4];"
        : "=r"(r[0]), "=r"(r[1]), "=r"(r[2]), "=r"(r[3]) : "r"(addr));
}
__device__ __forceinline__ float ex2f(float x) {
    float y;
    asm("ex2.approx.f32 %0, %1;" : "=f"(y) : "f"(x));
    return y;
}

// ================= dense fp16 TN GEMM (128x128, 256 thr, 2 CTA/SM) =================
// Prefetch issue moved to END of each iteration so ldsm stream enters the L1tex
// queue ahead of the LDGSTS burst (queue-contention fix).
#define STAGES 3
#define TILE_BYTES 16384
#define STAGE_BYTES 32768
#define SM_TOT (STAGES*STAGE_BYTES + 512)
#define BM 128
#define BN 128

// mode 0: plain fp32 C out
// mode 1: fused QKV epilogue: bn = head (0-31 q, 32-35 k, 36-39 v)
__global__ __launch_bounds__(256, 2) void gemm_h(
    const __half* __restrict__ A, const __half* __restrict__ B, float* __restrict__ C,
    int K, int lda, int ldb, int ldc, float scale,
    const int* __restrict__ positions, const float* __restrict__ qw,
    const float* __restrict__ kw, int mode)
{
    int bm = blockIdx.y, bn = blockIdx.x;

    extern __shared__ char smem[];
    uint32_t sbase = smem_u32(smem);

    int tid  = threadIdx.x;
    int warp = tid >> 5, lane = tid & 31;
    int wm = warp & 3, wn = warp >> 2;
    int r = lane >> 2, c = lane & 3;

    int arow_in = ((lane >> 3) & 1) * 8 + (lane & 7);
    int ahi = lane >> 4;
    int am7 = lane & 7;
    int bro = ((lane >> 4) << 3) + (lane & 7);
    int bcb = (lane >> 3) & 1;
    int bb7 = lane & 7;

    float acc[2][8][4];
#pragma unroll
    for (int i = 0; i < 2; i++)
#pragma unroll
        for (int j = 0; j < 8; j++)
#pragma unroll
            for (int k = 0; k < 4; k++) acc[i][j][k] = 0.f;

    int nkt = K >> 6;
    const __half* Ab = A + (long long)bm * BM * lda;
    const __half* Bb = B + (long long)bn * BN * ldb;

    int sm_ = tid >> 1;
    int scb = (tid & 1) * 4;
    long long arow = (long long)sm_ * lda;
    long long brow = (long long)sm_ * ldb;

#pragma unroll
    for (int p = 0; p < STAGES - 1; p++) {
        if (p < nkt) {
            int kb = p << 6;
            uint32_t aD = sbase + p * STAGE_BYTES + sm_ * 128;
            uint32_t bD = aD + TILE_BYTES;
            const __half* as = Ab + arow + kb + scb * 8;
            const __half* bs = Bb + brow + kb + scb * 8;
#pragma unroll
            for (int j = 0; j < 4; j++) {
                int sw = ((scb + j) ^ (sm_ & 7)) * 16;
                cp16(aD + sw, as + j * 8);
                cp16(bD + sw, bs + j * 8);
            }
        }
        asm volatile("cp.async.commit_group;" ::: "memory");
    }

    for (int kt = 0; kt < nkt; kt++) {
        asm volatile("cp.async.wait_group 1;" ::: "memory");
        __syncthreads();

        uint32_t sa  = sbase + (kt % STAGES) * STAGE_BYTES;
        uint32_t sbm = sa + TILE_BYTES;

        // ---- compute first: ldsm stream enters L1tex queue before LDGSTS burst ----
#pragma unroll
        for (int ks = 0; ks < 4; ks++) {
            unsigned a[2][4];
#pragma unroll
            for (int mt = 0; mt < 2; mt++) {
                uint32_t row = (uint32_t)(wm * 32 + mt * 16 + arow_in);
                ldsm4(a[mt], sa + row * 128u + ((unsigned)((2 * ks + ahi) ^ am7) << 4));
            }
#pragma unroll
            for (int ntp = 0; ntp < 4; ntp++) {
                unsigned bb[4];
                uint32_t row = (uint32_t)(wn * 64 + ntp * 16 + bro);
                ldsm4(bb, sbm + row * 128u + ((unsigned)((2 * ks + bcb) ^ bb7) << 4));
#pragma unroll
                for (int mt = 0; mt < 2; mt++) {
                    mma_f16(acc[mt][2 * ntp],     a[mt], bb);
                    mma_f16(acc[mt][2 * ntp + 1], a[mt], bb + 2);
                }
            }
        }

        // ---- issue prefetch for stage kt+2 at END of iteration ----
        // Safe: writes target stage (kt+2)%3 == (kt-1)%3, whose readers finished
        // before the top-of-kt barrier that every warp has already passed.
        if (kt + STAGES - 1 < nkt) {
            int kn = kt + STAGES - 1;
            int kb = kn << 6;
            uint32_t aD = sbase + (kn % STAGES) * STAGE_BYTES + sm_ * 128;
            uint32_t bD = aD + TILE_BYTES;
            const __half* as = Ab + arow + kb + scb * 8;
            const __half* bs = Bb + brow + kb + scb * 8;
#pragma unroll
            for (int j = 0; j < 4; j++) {
                int sw = ((scb + j) ^ (sm_ & 7)) * 16;
                cp16(aD + sw, as + j * 8);
                cp16(bD + sw, bs + j * 8);
            }
        }
        asm volatile("cp.async.commit_group;" ::: "memory");
    }

    asm volatile("cp.async.wait_group 0;" ::: "memory");

    if (mode == 0) {
#pragma unroll
        for (int mt = 0; mt < 2; mt++) {
            int m0 = bm * BM + wm * 32 + mt * 16 + r;
#pragma unroll
            for (int nt = 0; nt < 8; nt++) {
                int n0 = bn * BN + wn * 64 + nt * 8 + 2 * c;
                *(float2*)(C + (long long)m0 * ldc + n0) =
                    make_float2(acc[mt][nt][0] * scale, acc[mt][nt][1] * scale);
                *(float2*)(C + (long long)(m0 + 8) * ldc + n0) =
                    make_float2(acc[mt][nt][2] * scale, acc[mt][nt][3] * scale);
            }
        }
        return;
    }

    // ---- fused QKV epilogue: acc -> smem buf (128 x 132 fp32), then norm/rope/transpose ----
    __syncthreads();
    float* buf = (float*)smem;
#pragma unroll
    for (int mt = 0; mt < 2; mt++) {
        int mrow = wm * 32 + mt * 16 + r;
#pragma unroll
        for (int nt = 0; nt < 8; nt++) {
            int nc = wn * 64 + nt * 8 + 2 * c;
            *(float2*)(buf + mrow * 132 + nc)       = make_float2(acc[mt][nt][0], acc[mt][nt][1]);
            *(float2*)(buf + (mrow + 8) * 132 + nc) = make_float2(acc[mt][nt][2], acc[mt][nt][3]);
        }
    }
    __syncthreads();

    int h = bn;
    if (h < 36) {
        int row = tid >> 1, half = tid & 1;
        int t = bm * BM + row;
        const float* own = buf + row * 132 + half * 64;
        const float* par = buf + row * 132 + (half ^ 1) * 64;

        float ss = 0.f;
#pragma unroll
        for (int i = 0; i < 16; i++) {
            float4 v = *(const float4*)(own + i * 4);
            ss += v.x * v.x + v.y * v.y + v.z * v.z + v.w * v.w;
        }
        ss += __shfl_xor_sync(0xffffffffu, ss, 1);
        float rinv = rsqrtf(ss * (1.f / 128.f) + 1e-6f);

        const float* w_ = (h < 32) ? qw : kw;
        float pos = (float)positions[t];
        float osc = (h < 32) ? (ATT_SCALE * LOG2E) : 1.f;
        float sgn = half ? 1.f : -1.f;
        __half* outp;
        if (h < 32) outp = g_q + ((size_t)h * TT + t) * HD + half * 64;
        else        outp = g_k + ((size_t)(h - 32) * TT + t) * HD + half * 64;

#pragma unroll 8
        for (int i = 0; i < 64; i += 2) {
            float cs0 = 0.f, sn0 = 0.f, cs1 = 0.f, sn1 = 0.f;
            if (!(lane & 1)) {
                float a0 = pos * g_invf[i], a1 = pos * g_invf[i + 1];
                cs0 = cosf(a0); sn0 = sinf(a0);
                cs1 = cosf(a1); sn1 = sinf(a1);
            }
            cs0 = __shfl_sync(0xffffffffu, cs0, lane & ~1);
            sn0 = __shfl_sync(0xffffffffu, sn0, lane & ~1);
            cs1 = __shfl_sync(0xffffffffu, cs1, lane & ~1);
            sn1 = __shfl_sync(0xffffffffu, sn1, lane & ~1);
            float y0 = own[i]     * rinv * w_[half * 64 + i];
            float y1 = own[i + 1] * rinv * w_[half * 64 + i + 1];
            float z0 = par[i]     * rinv * w_[(half ^ 1) * 64 + i];
            float z1 = par[i + 1] * rinv * w_[(half ^ 1) * 64 + i + 1];
            float o0 = (y0 * cs0 + sgn * z0 * sn0) * osc;
            float o1 = (y1 * cs1 + sgn * z1 * sn1) * osc;
            *(__half2*)(outp + i) = __floats2half2_rn(o0, o1);
        }
    } else {
        int d = tid >> 1, thalf = tid & 1;
        int kvh = h - 36;
        __half* vp = g_vt + ((size_t)kvh * HD + d) * TT + (size_t)bm * BM + thalf * 64;
#pragma unroll 8
        for (int j2 = 0; j2 < 64; j2 += 2) {
            float v0 = buf[(thalf * 64 + j2) * 132 + d];
            float v1 = buf[(thalf * 64 + j2 + 1) * 132 + d];
            *(__half2*)(vp + j2) = __floats2half2_rn(v0, v1);
        }
    }
}

// ================= fused flash attention: q64, 256 thr, 2 CTA/SM, loads issued post-compute =================
// smem: Q 16KB | K0 32KB | K1 32KB | V 32KB | lsum 512B.  O-reduction reuses K0 (32KB).
#define F3_Q  0
#define F3_K0 16384
#define F3_K1 49152
#define F3_V  81920
#define F3_L  114688
#define F3_TOT (F3_L + 512 + 128)

// K tile: 128 rows x 128 halves, 2 sub-tiles of 16KB, 256 threads
__device__ __forceinline__ void fl_load128(
    uint32_t sdst, const __half* src, long long ld, int tid)
{
#pragma unroll
    for (int i = 0; i < 8; i++) {
        int li = tid + 256 * i;
        int row = li >> 4, cc = li & 15;
        uint32_t dst = sdst + (cc >> 3) * 16384 + row * 128 + (((cc & 7) ^ (row & 7)) * 16);
        cp16(dst, src + (long long)row * ld + cc * 8);
    }
}

__global__ __launch_bounds__(256, 2) void flash_kernel()
{
    int b = blockIdx.x;
    int bm = 31 - (b >> 5);     // q-block of 64 rows; heavy first
    int h  = b & 31;
    int kvh = h >> 3;

    extern __shared__ char sm[];
    uint32_t sbase = smem_u32(sm);
    float* lsum = (float*)(sm + F3_L);

    int tid = threadIdx.x;
    int w = tid >> 5, lane = tid & 31;
    int wm = w & 3, wn = w >> 2;
    int r = lane >> 2, c = lane & 3;

    int am  = wm * 16 + ((lane >> 3) & 1) * 8 + (lane & 7);
    int am7 = am & 7;
    int ahi = lane >> 4;
    uint32_t aoff = (uint32_t)am * 128u;
    int bro = ((lane >> 4) << 3) + (lane & 7);
    int bcb = (lane >> 3) & 1;
    int bb7 = bro & 7;

    const __half* qsrc = g_q + ((size_t)h * TT + (size_t)bm * 64) * HD;
    const __half* ksrc = g_k + (size_t)kvh * TT * HD;
    const __half* vsrc = g_vt + (size_t)kvh * HD * TT;

    int nj = (bm >> 1) + 1;

    // prologue: GA = Q(64x128) + K(0) + V(0); GB = K(1)
#pragma unroll
    for (int i = 0; i < 4; i++) {
        int li = tid + 256 * i;
        int row = li >> 4, cc = li & 15;   // row 0..63
        uint32_t dst = sbase + F3_Q + (cc >> 3) * 8192 + row * 128 + (((cc & 7) ^ (row & 7)) * 16);
        cp16(dst, qsrc + (long long)row * HD + cc * 8);
    }
    fl_load128(sbase + F3_K0, ksrc, HD, tid);
#pragma unroll
    for (int i = 0; i < 8; i++) {
        int li = tid + 256 * i;
        int row = li >> 4, cc = li & 15;
        uint32_t dst = sbase + F3_V + (cc >> 3) * 16384 + row * 128 + (((cc & 7) ^ (row & 7)) * 16);
        cp16(dst, vsrc + (size_t)row * TT + cc * 8);
    }
    asm volatile("cp.async.commit_group;" ::: "memory");
    if (nj > 1)
        fl_load128(sbase + F3_K1, ksrc + (size_t)128 * HD, HD, tid);
    asm volatile("cp.async.commit_group;" ::: "memory");

    float acc_o[16][4];
#pragma unroll
    for (int i = 0; i < 16; i++)
#pragma unroll
        for (int k = 0; k < 4; k++) acc_o[i][k] = 0.f;
    float l0a = 0.f, l0b = 0.f, l1a = 0.f, l1b = 0.f;

    int mrow0 = wm * 16 + r;            // local q row (0..63)

    for (int j = 0; j < nj; j++) {
        uint32_t kbuf = sbase + ((j & 1) ? F3_K1 : F3_K0);

        // top: K(j) ready (j=0: GA has Q,K0,V0; j>0: two newest groups may pend)
        if (j == 0) { asm volatile("cp.async.wait_group 1;" ::: "memory"); }
        else        { asm volatile("cp.async.wait_group 2;" ::: "memory"); }
        __syncthreads();

        // ---- S = Q @ K^T (Q pre-scaled by d^-1/2 * log2e) ----
        float acc_s[8][4];
#pragma unroll
        for (int i = 0; i < 8; i++)
#pragma unroll
            for (int k = 0; k < 4; k++) acc_s[i][k] = 0.f;

        uint32_t squ = sbase + F3_Q;
#pragma unroll
        for (int kt = 0; kt < 2; kt++) {
#pragma unroll
            for (int ks = 0; ks < 4; ks++) {
                unsigned a[4];
                ldsm4(a, squ + kt * 8192 + aoff + ((unsigned)((2 * ks + ahi) ^ am7) << 4));
#pragma unroll
                for (int ntp = 0; ntp < 4; ntp++) {
                    unsigned bb[4];
                    ldsm4(bb, kbuf + kt * 16384 + (unsigned)(wn * 64 + ntp * 16 + bro) * 128
                              + ((unsigned)((2 * ks + bcb) ^ bb7) << 4));
                    mma_f16(acc_s[2 * ntp],     a, bb);
                    mma_f16(acc_s[2 * ntp + 1], a, bb + 2);
                }
            }
        }

        // V(j) ready (j=0: already in GA; wait is a no-op)
        asm volatile("cp.async.wait_group 1;" ::: "memory");
        __syncthreads();

        // ---- interleaved exp2/mask/pack + PV mma (per ks-chunk) ----
        bool diag = (j == nj - 1);
        int lim = bm * 64 + mrow0 - j * 128;   // causal limit (local kv index)
        uint32_t svu = sbase + F3_V + wn * 16384;
#pragma unroll
        for (int ks = 0; ks < 4; ks++) {
            unsigned a[4];
#pragma unroll
            for (int q = 0; q < 2; q++) {
                int nt = 2 * ks + q;
                int n0 = wn * 64 + nt * 8 + 2 * c;
                float v0 = ex2f(acc_s[nt][0] - EXP_SHIFT_L2);
                float v1 = ex2f(acc_s[nt][1] - EXP_SHIFT_L2);
                float v2 = ex2f(acc_s[nt][2] - EXP_SHIFT_L2);
                float v3 = ex2f(acc_s[nt][3] - EXP_SHIFT_L2);
                if (diag) {
                    if (n0     > lim)     v0 = 0.f;
                    if (n0 + 1 > lim)     v1 = 0.f;
                    if (n0     > lim + 8) v2 = 0.f;
                    if (n0 + 1 > lim + 8) v3 = 0.f;
                }
                if (q == 0) { l0a += v0 + v1; l1a += v2 + v3; }
                else        { l0b += v0 + v1; l1b += v2 + v3; }
                __half2 h01 = __floats2half2_rn(v0, v1);
                __half2 h23 = __floats2half2_rn(v2, v3);
                a[2 * q]     = *(unsigned*)&h01;
                a[2 * q + 1] = *(unsigned*)&h23;
            }
#pragma unroll
            for (int dnp = 0; dnp < 8; dnp++) {
                unsigned bb[4];
                ldsm4(bb, svu + (unsigned)(dnp * 16 + bro) * 128
                          + ((unsigned)((2 * ks + bcb) ^ bb7) << 4));
                mma_f16(acc_o[2 * dnp],     a, bb);
                mma_f16(acc_o[2 * dnp + 1], a, bb + 2);
            }
        }

        // ---- end of iteration: issue next loads AFTER compute (queue-contention fix) ----
        __syncthreads();   // all warps done reading V(j) (PV) and K(j) (S)
        if (j + 1 < nj) {
            // V(j+1) into the single V buffer
#pragma unroll
            for (int i = 0; i < 8; i++) {
                int li = tid + 256 * i;
                int row = li >> 4, cc = li & 15;
                uint32_t dst = sbase + F3_V + (cc >> 3) * 16384 + row * 128
                             + (((cc & 7) ^ (row & 7)) * 16);
                cp16(dst, vsrc + (size_t)row * TT + (j + 1) * 128 + cc * 8);
            }
        }
        asm volatile("cp.async.commit_group;" ::: "memory");   // group V_{j+1}
        if (j + 2 < nj)
            fl_load128(sbase + (((j + 2) & 1) ? F3_K1 : F3_K0),
                       ksrc + (size_t)(j + 2) * 128 * HD, HD, tid);
        asm volatile("cp.async.commit_group;" ::: "memory");   // group K_{j+2}
    }

    asm volatile("cp.async.wait_group 0;" ::: "memory");

    // ---- cross-slice reduction + normalize + write ----
    __syncthreads();
    float* red = (float*)(sm + F3_K0);   // 32KB, K0 buffer retired

    if (wn == 1) {
        float* dst = red + wm * 2048;    // 16 rows x 128 floats
#pragma unroll
        for (int dn = 0; dn < 16; dn++) {
            *(float2*)(dst + r * 128 + dn * 8 + 2 * c)       = make_float2(acc_o[dn][0], acc_o[dn][1]);
            *(float2*)(dst + (r + 8) * 128 + dn * 8 + 2 * c) = make_float2(acc_o[dn][2], acc_o[dn][3]);
        }
    }
    float l0 = l0a + l0b, l1 = l1a + l1b;
    l0 += __shfl_xor_sync(0xffffffffu, l0, 1);
    l0 += __shfl_xor_sync(0xffffffffu, l0, 2);
    l1 += __shfl_xor_sync(0xffffffffu, l1, 1);
    l1 += __shfl_xor_sync(0xffffffffu, l1, 2);
    if (c == 0) {
        lsum[wn * 64 + wm * 16 + r]     = l0;
        lsum[wn * 64 + wm * 16 + r + 8] = l1;
    }
    __syncthreads();

    if (wn == 0) {
        int row0 = wm * 16 + r;
        float inv0 = 1.f / (lsum[row0]     + lsum[64 + row0]);
        float inv1 = 1.f / (lsum[row0 + 8] + lsum[64 + row0 + 8]);
        const float* src = red + wm * 2048;
        __half* o0 = g_attn + (size_t)(bm * 64 + row0) * QS + h * 128;
        __half* o1 = g_attn + (size_t)(bm * 64 + row0 + 8) * QS + h * 128;
#pragma unroll
        for (int dn = 0; dn < 16; dn++) {
            int nc = dn * 8 + 2 * c;
            float2 s0 = *(const float2*)(src + r * 128 + nc);
            float2 s1 = *(const float2*)(src + (r + 8) * 128 + nc);
            *(__half2*)(o0 + nc) = __floats2half2_rn((acc_o[dn][0] + s0.x) * inv0,
                                                     (acc_o[dn][1] + s0.y) * inv0);
            *(__half2*)(o1 + nc) = __floats2half2_rn((acc_o[dn][2] + s1.x) * inv1,
                                                     (acc_o[dn][3] + s1.y) * inv1);
        }
    }
}

// ---------------- fp32 -> fp16 conversion (all three arrays + invf, one launch) ----------------
#define N4_HID  (TT * HIDDEN / 4)
#define N4_WQKV (QKVN * HIDDEN / 4)
#define N4_WO   (HIDDEN * QS / 4)
__global__ void h_conv_all(const float4* __restrict__ s0, uint2* __restrict__ d0,
                           const float4* __restrict__ s1, uint2* __restrict__ d1,
                           const float4* __restrict__ s2, uint2* __restrict__ d2) {
    if (blockIdx.x == 0 && threadIdx.x < 64)
        g_invf[threadIdx.x] = (float)exp(-(double)threadIdx.x * (log(10000.0) / 64.0));
    int i = blockIdx.x * 256 + threadIdx.x;
    int stride = gridDim.x * 256;
    int ntot = N4_HID + N4_WQKV + N4_WO;
    for (; i < ntot; i += stride) {
        const float4* s; uint2* d; int idx;
        if (i < N4_HID)              { s = s0; d = d0; idx = i; }
        else if (i < N4_HID + N4_WQKV) { s = s1; d = d1; idx = i - N4_HID; }
        else                         { s = s2; d = d2; idx = i - N4_HID - N4_WQKV; }
        float4 v = s[idx];
        __half2 lo = __floats2half2_rn(v.x, v.y);
        __half2 hi = __floats2half2_rn(v.z, v.w);
        uint2 o;
        o.x = *(unsigned*)&lo;
        o.y = *(unsigned*)&hi;
        d[idx] = o;
    }
}

// ---------------- launcher ----------------
extern "C" void kernel_launch(void* const* d_in, const int* in_sizes, int n_in,
                              void* d_out, int out_size)
{
    const int* positions = (const int*)d_in[0];   // int32 (JAX x64 disabled)
    const float* hidden = (const float*)d_in[1];
    const float* w_qkv  = (const float*)d_in[2];
    const float* w_o    = (const float*)d_in[3];
    const float* qw     = (const float*)d_in[4];
    const float* kw     = (const float*)d_in[5];
    float* out = (float*)d_out;

    __half *p_attn, *p_hidh, *p_wqkvh, *p_woh;
    cudaGetSymbolAddress((void**)&p_attn,  g_attn);
    cudaGetSymbolAddress((void**)&p_hidh,  g_hidh);
    cudaGetSymbolAddress((void**)&p_wqkvh, g_wqkvh);
    cudaGetSymbolAddress((void**)&p_woh,   g_woh);

    cudaFuncSetAttribute(gemm_h, cudaFuncAttributeMaxDynamicSharedMemorySize, SM_TOT);
    cudaFuncSetAttribute(flash_kernel, cudaFuncAttributeMaxDynamicSharedMemorySize, F3_TOT);

    // 0) fp16 conversions + invf (one launch)
    h_conv_all<<<2048, 256>>>((const float4*)hidden, (uint2*)p_hidh,
                              (const float4*)w_qkv,  (uint2*)p_wqkvh,
                              (const float4*)w_o,    (uint2*)p_woh);

    // 1) QKV projection with fused RMSNorm+RoPE+reorder epilogue
    gemm_h<<<dim3(QKVN / BN, TT / BM, 1), 256, SM_TOT>>>(
        p_hidh, p_wqkvh, nullptr, HIDDEN, HIDDEN, HIDDEN, 0, 1.0f,
        positions, qw, kw, 1);

    // 2) fused flash attention (64-row q-tiles, 2 CTA/SM, post-compute load issue) -> g_attn
    flash_kernel<<<1024, 256, F3_TOT>>>();

    // 3) output projection (fp32 out)
    gemm_h<<<dim3(HIDDEN / BN, TT / BM, 1), 256, SM_TOT>>>(
        p_attn, p_woh, out, QS, QS, QS, HIDDEN, 1.0f,
        nullptr, nullptr, nullptr, 0);
}

// round 16
// speedup vs baseline: 1.1049x; 1.0200x over previous
#include <cuda_runtime.h>
#include <cuda_fp16.h>
#include <math.h>
#include <float.h>
#include <stdint.h>

#define TT 2048
#define HIDDEN 2048
#define NH 32
#define NKV 4
#define HD 128
#define QS (NH*HD)        // 4096
#define KVS (NKV*HD)      // 512
#define QKVN (QS + 2*KVS) // 5120

// ---------------- scratch (static device globals; no allocs) ----------------
__device__ __half g_q   [(size_t)NH * TT * HD];   //  16 MB [h][t][d]  (pre-scaled by d^-1/2 * log2e)
__device__ __half g_k   [(size_t)NKV * TT * HD];  //   2 MB [kv][t][d]
__device__ __half g_vt  [(size_t)NKV * HD * TT];  //   2 MB [kv][d][t]
__device__ __half g_attn[(size_t)TT * QS];        //  16 MB [t][h*128+d]
__device__ __half g_hidh [(size_t)TT * HIDDEN];   //   8 MB fp16(hidden)
__device__ __half g_wqkvh[(size_t)QKVN * HIDDEN]; //  20 MB fp16(w_qkv)
__device__ __half g_woh  [(size_t)HIDDEN * QS];   //  16 MB fp16(w_o)
__device__ float  g_invf[64];

#define ATT_SCALE 0.08838834764831845f
#define LOG2E 1.4426950408889634f
#define EXP_SHIFT_L2 5.7707801635558535f   // 4 * log2(e)

// ---------------- helpers ----------------
__device__ __forceinline__ uint32_t smem_u32(const void* p) {
    uint32_t a;
    asm("{ .reg .u64 t; cvta.to.shared.u64 t, %1; cvt.u32.u64 %0, t; }" : "=r"(a) : "l"(p));
    return a;
}
__device__ __forceinline__ void cp16(uint32_t dst, const void* src) {
    asm volatile("cp.async.cg.shared.global [%0], [%1], 16;" :: "r"(dst), "l"(src));
}
__device__ __forceinline__ void mma_f16(float* d, const unsigned* a, const unsigned* b) {
    asm volatile(
        "mma.sync.aligned.m16n8k16.row.col.f32.f16.f16.f32 "
        "{%0,%1,%2,%3}, {%4,%5,%6,%7}, {%8,%9}, {%0,%1,%2,%3};\n"
        : "+f"(d[0]), "+f"(d[1]), "+f"(d[2]), "+f"(d[3])
        : "r"(a[0]), "r"(a[1]), "r"(a[2]), "r"(a[3]), "r"(b[0]), "r"(b[1]));
}
__device__ __forceinline__ void ldsm4(unsigned* r, uint32_t addr) {
    asm volatile("ldmatrix.sync.aligned.m8n8.x4.shared.b16 {%0,%1,%2,%3}, [%4];"
        : "=r"(r[0]), "=r"(r[1]), "=r"(r[2]), "=r"(r[3]) : "r"(addr));
}
__device__ __forceinline__ float ex2f(float x) {
    float y;
    asm("ex2.approx.f32 %0, %1;" : "=f"(y) : "f"(x));
    return y;
}

// ================= dense fp16 TN GEMM (128x128, 256 thr, 2 CTA/SM) =================
// Software-pipelined B-fragment loads: ldsm(next) issued before mma(current).
#define STAGES 3
#define TILE_BYTES 16384
#define STAGE_BYTES 32768
#define SM_TOT (STAGES*STAGE_BYTES + 512)
#define BM 128
#define BN 128

// mode 0: plain fp32 C out
// mode 1: fused QKV epilogue: bn = head (0-31 q, 32-35 k, 36-39 v)
__global__ __launch_bounds__(256, 2) void gemm_h(
    const __half* __restrict__ A, const __half* __restrict__ B, float* __restrict__ C,
    int K, int lda, int ldb, int ldc, float scale,
    const int* __restrict__ positions, const float* __restrict__ qw,
    const float* __restrict__ kw, int mode)
{
    int bm = blockIdx.y, bn = blockIdx.x;

    extern __shared__ char smem[];
    uint32_t sbase = smem_u32(smem);

    int tid  = threadIdx.x;
    int warp = tid >> 5, lane = tid & 31;
    int wm = warp & 3, wn = warp >> 2;
    int r = lane >> 2, c = lane & 3;

    int arow_in = ((lane >> 3) & 1) * 8 + (lane & 7);
    int ahi = lane >> 4;
    int am7 = lane & 7;
    int bro = ((lane >> 4) << 3) + (lane & 7);
    int bcb = (lane >> 3) & 1;
    int bb7 = lane & 7;

    float acc[2][8][4];
#pragma unroll
    for (int i = 0; i < 2; i++)
#pragma unroll
        for (int j = 0; j < 8; j++)
#pragma unroll
            for (int k = 0; k < 4; k++) acc[i][j][k] = 0.f;

    int nkt = K >> 6;
    const __half* Ab = A + (long long)bm * BM * lda;
    const __half* Bb = B + (long long)bn * BN * ldb;

    int sm_ = tid >> 1;
    int scb = (tid & 1) * 4;
    long long arow = (long long)sm_ * lda;
    long long brow = (long long)sm_ * ldb;

    uint32_t arow0 = (uint32_t)(wm * 32 + arow_in);
    uint32_t arow1 = arow0 + 16;
    uint32_t brow0 = (uint32_t)(wn * 64 + bro);

#pragma unroll
    for (int p = 0; p < STAGES - 1; p++) {
        if (p < nkt) {
            int kb = p << 6;
            uint32_t aD = sbase + p * STAGE_BYTES + sm_ * 128;
            uint32_t bD = aD + TILE_BYTES;
            const __half* as = Ab + arow + kb + scb * 8;
            const __half* bs = Bb + brow + kb + scb * 8;
#pragma unroll
            for (int j = 0; j < 4; j++) {
                int sw = ((scb + j) ^ (sm_ & 7)) * 16;
                cp16(aD + sw, as + j * 8);
                cp16(bD + sw, bs + j * 8);
            }
        }
        asm volatile("cp.async.commit_group;" ::: "memory");
    }

    for (int kt = 0; kt < nkt; kt++) {
        asm volatile("cp.async.wait_group 1;" ::: "memory");
        __syncthreads();

        uint32_t sa  = sbase + (kt % STAGES) * STAGE_BYTES;
        uint32_t sbm = sa + TILE_BYTES;

        // ---- compute, software-pipelined fragment loads ----
        unsigned a[2][4], bbc[4], bbn[4];
        ldsm4(a[0], sa + arow0 * 128u + ((unsigned)((0 + ahi) ^ am7) << 4));
        ldsm4(a[1], sa + arow1 * 128u + ((unsigned)((0 + ahi) ^ am7) << 4));
        ldsm4(bbc,  sbm + brow0 * 128u + ((unsigned)((0 + bcb) ^ bb7) << 4));
#pragma unroll
        for (int ks = 0; ks < 4; ks++) {
#pragma unroll
            for (int ntp = 0; ntp < 4; ntp++) {
                if (ntp < 3) {
                    ldsm4(bbn, sbm + (brow0 + (ntp + 1) * 16) * 128u
                               + ((unsigned)((2 * ks + bcb) ^ bb7) << 4));
                } else if (ks < 3) {
                    ldsm4(bbn, sbm + brow0 * 128u
                               + ((unsigned)((2 * (ks + 1) + bcb) ^ bb7) << 4));
                }
                mma_f16(acc[0][2 * ntp],     a[0], bbc);
                mma_f16(acc[0][2 * ntp + 1], a[0], bbc + 2);
                mma_f16(acc[1][2 * ntp],     a[1], bbc);
                mma_f16(acc[1][2 * ntp + 1], a[1], bbc + 2);
                bbc[0] = bbn[0]; bbc[1] = bbn[1]; bbc[2] = bbn[2]; bbc[3] = bbn[3];
            }
            if (ks < 3) {
                ldsm4(a[0], sa + arow0 * 128u + ((unsigned)((2 * (ks + 1) + ahi) ^ am7) << 4));
                ldsm4(a[1], sa + arow1 * 128u + ((unsigned)((2 * (ks + 1) + ahi) ^ am7) << 4));
            }
        }

        // ---- issue prefetch for stage kt+2 at END of iteration ----
        if (kt + STAGES - 1 < nkt) {
            int kn = kt + STAGES - 1;
            int kb = kn << 6;
            uint32_t aD = sbase + (kn % STAGES) * STAGE_BYTES + sm_ * 128;
            uint32_t bD = aD + TILE_BYTES;
            const __half* as = Ab + arow + kb + scb * 8;
            const __half* bs = Bb + brow + kb + scb * 8;
#pragma unroll
            for (int j = 0; j < 4; j++) {
                int sw = ((scb + j) ^ (sm_ & 7)) * 16;
                cp16(aD + sw, as + j * 8);
                cp16(bD + sw, bs + j * 8);
            }
        }
        asm volatile("cp.async.commit_group;" ::: "memory");
    }

    asm volatile("cp.async.wait_group 0;" ::: "memory");

    if (mode == 0) {
#pragma unroll
        for (int mt = 0; mt < 2; mt++) {
            int m0 = bm * BM + wm * 32 + mt * 16 + r;
#pragma unroll
            for (int nt = 0; nt < 8; nt++) {
                int n0 = bn * BN + wn * 64 + nt * 8 + 2 * c;
                *(float2*)(C + (long long)m0 * ldc + n0) =
                    make_float2(acc[mt][nt][0] * scale, acc[mt][nt][1] * scale);
                *(float2*)(C + (long long)(m0 + 8) * ldc + n0) =
                    make_float2(acc[mt][nt][2] * scale, acc[mt][nt][3] * scale);
            }
        }
        return;
    }

    // ---- fused QKV epilogue: acc -> smem buf (128 x 132 fp32), then norm/rope/transpose ----
    __syncthreads();
    float* buf = (float*)smem;
#pragma unroll
    for (int mt = 0; mt < 2; mt++) {
        int mrow = wm * 32 + mt * 16 + r;
#pragma unroll
        for (int nt = 0; nt < 8; nt++) {
            int nc = wn * 64 + nt * 8 + 2 * c;
            *(float2*)(buf + mrow * 132 + nc)       = make_float2(acc[mt][nt][0], acc[mt][nt][1]);
            *(float2*)(buf + (mrow + 8) * 132 + nc) = make_float2(acc[mt][nt][2], acc[mt][nt][3]);
        }
    }
    __syncthreads();

    int h = bn;
    if (h < 36) {
        int row = tid >> 1, half = tid & 1;
        int t = bm * BM + row;
        const float* own = buf + row * 132 + half * 64;
        const float* par = buf + row * 132 + (half ^ 1) * 64;

        float ss = 0.f;
#pragma unroll
        for (int i = 0; i < 16; i++) {
            float4 v = *(const float4*)(own + i * 4);
            ss += v.x * v.x + v.y * v.y + v.z * v.z + v.w * v.w;
        }
        ss += __shfl_xor_sync(0xffffffffu, ss, 1);
        float rinv = rsqrtf(ss * (1.f / 128.f) + 1e-6f);

        const float* w_ = (h < 32) ? qw : kw;
        float pos = (float)positions[t];
        float osc = (h < 32) ? (ATT_SCALE * LOG2E) : 1.f;
        float sgn = half ? 1.f : -1.f;
        __half* outp;
        if (h < 32) outp = g_q + ((size_t)h * TT + t) * HD + half * 64;
        else        outp = g_k + ((size_t)(h - 32) * TT + t) * HD + half * 64;

#pragma unroll 8
        for (int i = 0; i < 64; i += 2) {
            float cs0 = 0.f, sn0 = 0.f, cs1 = 0.f, sn1 = 0.f;
            if (!(lane & 1)) {
                float a0 = pos * g_invf[i], a1 = pos * g_invf[i + 1];
                cs0 = cosf(a0); sn0 = sinf(a0);
                cs1 = cosf(a1); sn1 = sinf(a1);
            }
            cs0 = __shfl_sync(0xffffffffu, cs0, lane & ~1);
            sn0 = __shfl_sync(0xffffffffu, sn0, lane & ~1);
            cs1 = __shfl_sync(0xffffffffu, cs1, lane & ~1);
            sn1 = __shfl_sync(0xffffffffu, sn1, lane & ~1);
            float y0 = own[i]     * rinv * w_[half * 64 + i];
            float y1 = own[i + 1] * rinv * w_[half * 64 + i + 1];
            float z0 = par[i]     * rinv * w_[(half ^ 1) * 64 + i];
            float z1 = par[i + 1] * rinv * w_[(half ^ 1) * 64 + i + 1];
            float o0 = (y0 * cs0 + sgn * z0 * sn0) * osc;
            float o1 = (y1 * cs1 + sgn * z1 * sn1) * osc;
            *(__half2*)(outp + i) = __floats2half2_rn(o0, o1);
        }
    } else {
        int d = tid >> 1, thalf = tid & 1;
        int kvh = h - 36;
        __half* vp = g_vt + ((size_t)kvh * HD + d) * TT + (size_t)bm * BM + thalf * 64;
#pragma unroll 8
        for (int j2 = 0; j2 < 64; j2 += 2) {
            float v0 = buf[(thalf * 64 + j2) * 132 + d];
            float v1 = buf[(thalf * 64 + j2 + 1) * 132 + d];
            *(__half2*)(vp + j2) = __floats2half2_rn(v0, v1);
        }
    }
}

// ================= fused flash attention: q64, 256 thr, 2 CTA/SM, loads issued post-compute =================
#define F3_Q  0
#define F3_K0 16384
#define F3_K1 49152
#define F3_V  81920
#define F3_L  114688
#define F3_TOT (F3_L + 512 + 128)

__device__ __forceinline__ void fl_load128(
    uint32_t sdst, const __half* src, long long ld, int tid)
{
#pragma unroll
    for (int i = 0; i < 8; i++) {
        int li = tid + 256 * i;
        int row = li >> 4, cc = li & 15;
        uint32_t dst = sdst + (cc >> 3) * 16384 + row * 128 + (((cc & 7) ^ (row & 7)) * 16);
        cp16(dst, src + (long long)row * ld + cc * 8);
    }
}

__global__ __launch_bounds__(256, 2) void flash_kernel()
{
    int b = blockIdx.x;
    int bm = 31 - (b >> 5);     // q-block of 64 rows; heavy first
    int h  = b & 31;
    int kvh = h >> 3;

    extern __shared__ char sm[];
    uint32_t sbase = smem_u32(sm);
    float* lsum = (float*)(sm + F3_L);

    int tid = threadIdx.x;
    int w = tid >> 5, lane = tid & 31;
    int wm = w & 3, wn = w >> 2;
    int r = lane >> 2, c = lane & 3;

    int am  = wm * 16 + ((lane >> 3) & 1) * 8 + (lane & 7);
    int am7 = am & 7;
    int ahi = lane >> 4;
    uint32_t aoff = (uint32_t)am * 128u;
    int bro = ((lane >> 4) << 3) + (lane & 7);
    int bcb = (lane >> 3) & 1;
    int bb7 = bro & 7;

    const __half* qsrc = g_q + ((size_t)h * TT + (size_t)bm * 64) * HD;
    const __half* ksrc = g_k + (size_t)kvh * TT * HD;
    const __half* vsrc = g_vt + (size_t)kvh * HD * TT;

    int nj = (bm >> 1) + 1;

#pragma unroll
    for (int i = 0; i < 4; i++) {
        int li = tid + 256 * i;
        int row = li >> 4, cc = li & 15;
        uint32_t dst = sbase + F3_Q + (cc >> 3) * 8192 + row * 128 + (((cc & 7) ^ (row & 7)) * 16);
        cp16(dst, qsrc + (long long)row * HD + cc * 8);
    }
    fl_load128(sbase + F3_K0, ksrc, HD, tid);
#pragma unroll
    for (int i = 0; i < 8; i++) {
        int li = tid + 256 * i;
        int row = li >> 4, cc = li & 15;
        uint32_t dst = sbase + F3_V + (cc >> 3) * 16384 + row * 128 + (((cc & 7) ^ (row & 7)) * 16);
        cp16(dst, vsrc + (size_t)row * TT + cc * 8);
    }
    asm volatile("cp.async.commit_group;" ::: "memory");
    if (nj > 1)
        fl_load128(sbase + F3_K1, ksrc + (size_t)128 * HD, HD, tid);
    asm volatile("cp.async.commit_group;" ::: "memory");

    float acc_o[16][4];
#pragma unroll
    for (int i = 0; i < 16; i++)
#pragma unroll
        for (int k = 0; k < 4; k++) acc_o[i][k] = 0.f;
    float l0a = 0.f, l0b = 0.f, l1a = 0.f, l1b = 0.f;

    int mrow0 = wm * 16 + r;

    for (int j = 0; j < nj; j++) {
        uint32_t kbuf = sbase + ((j & 1) ? F3_K1 : F3_K0);

        if (j == 0) { asm volatile("cp.async.wait_group 1;" ::: "memory"); }
        else        { asm volatile("cp.async.wait_group 2;" ::: "memory"); }
        __syncthreads();

        float acc_s[8][4];
#pragma unroll
        for (int i = 0; i < 8; i++)
#pragma unroll
            for (int k = 0; k < 4; k++) acc_s[i][k] = 0.f;

        uint32_t squ = sbase + F3_Q;
#pragma unroll
        for (int kt = 0; kt < 2; kt++) {
#pragma unroll
            for (int ks = 0; ks < 4; ks++) {
                unsigned a[4];
                ldsm4(a, squ + kt * 8192 + aoff + ((unsigned)((2 * ks + ahi) ^ am7) << 4));
#pragma unroll
                for (int ntp = 0; ntp < 4; ntp++) {
                    unsigned bb[4];
                    ldsm4(bb, kbuf + kt * 16384 + (unsigned)(wn * 64 + ntp * 16 + bro) * 128
                              + ((unsigned)((2 * ks + bcb) ^ bb7) << 4));
                    mma_f16(acc_s[2 * ntp],     a, bb);
                    mma_f16(acc_s[2 * ntp + 1], a, bb + 2);
                }
            }
        }

        asm volatile("cp.async.wait_group 1;" ::: "memory");
        __syncthreads();

        bool diag = (j == nj - 1);
        int lim = bm * 64 + mrow0 - j * 128;
        uint32_t svu = sbase + F3_V + wn * 16384;
#pragma unroll
        for (int ks = 0; ks < 4; ks++) {
            unsigned a[4];
#pragma unroll
            for (int q = 0; q < 2; q++) {
                int nt = 2 * ks + q;
                int n0 = wn * 64 + nt * 8 + 2 * c;
                float v0 = ex2f(acc_s[nt][0] - EXP_SHIFT_L2);
                float v1 = ex2f(acc_s[nt][1] - EXP_SHIFT_L2);
                float v2 = ex2f(acc_s[nt][2] - EXP_SHIFT_L2);
                float v3 = ex2f(acc_s[nt][3] - EXP_SHIFT_L2);
                if (diag) {
                    if (n0     > lim)     v0 = 0.f;
                    if (n0 + 1 > lim)     v1 = 0.f;
                    if (n0     > lim + 8) v2 = 0.f;
                    if (n0 + 1 > lim + 8) v3 = 0.f;
                }
                if (q == 0) { l0a += v0 + v1; l1a += v2 + v3; }
                else        { l0b += v0 + v1; l1b += v2 + v3; }
                __half2 h01 = __floats2half2_rn(v0, v1);
                __half2 h23 = __floats2half2_rn(v2, v3);
                a[2 * q]     = *(unsigned*)&h01;
                a[2 * q + 1] = *(unsigned*)&h23;
            }
#pragma unroll
            for (int dnp = 0; dnp < 8; dnp++) {
                unsigned bb[4];
                ldsm4(bb, svu + (unsigned)(dnp * 16 + bro) * 128
                          + ((unsigned)((2 * ks + bcb) ^ bb7) << 4));
                mma_f16(acc_o[2 * dnp],     a, bb);
                mma_f16(acc_o[2 * dnp + 1], a, bb + 2);
            }
        }

        __syncthreads();
        if (j + 1 < nj) {
#pragma unroll
            for (int i = 0; i < 8; i++) {
                int li = tid + 256 * i;
                int row = li >> 4, cc = li & 15;
                uint32_t dst = sbase + F3_V + (cc >> 3) * 16384 + row * 128
                             + (((cc & 7) ^ (row & 7)) * 16);
                cp16(dst, vsrc + (size_t)row * TT + (j + 1) * 128 + cc * 8);
            }
        }
        asm volatile("cp.async.commit_group;" ::: "memory");
        if (j + 2 < nj)
            fl_load128(sbase + (((j + 2) & 1) ? F3_K1 : F3_K0),
                       ksrc + (size_t)(j + 2) * 128 * HD, HD, tid);
        asm volatile("cp.async.commit_group;" ::: "memory");
    }

    asm volatile("cp.async.wait_group 0;" ::: "memory");

    __syncthreads();
    float* red = (float*)(sm + F3_K0);

    if (wn == 1) {
        float* dst = red + wm * 2048;
#pragma unroll
        for (int dn = 0; dn < 16; dn++) {
            *(float2*)(dst + r * 128 + dn * 8 + 2 * c)       = make_float2(acc_o[dn][0], acc_o[dn][1]);
            *(float2*)(dst + (r + 8) * 128 + dn * 8 + 2 * c) = make_float2(acc_o[dn][2], acc_o[dn][3]);
        }
    }
    float l0 = l0a + l0b, l1 = l1a + l1b;
    l0 += __shfl_xor_sync(0xffffffffu, l0, 1);
    l0 += __shfl_xor_sync(0xffffffffu, l0, 2);
    l1 += __shfl_xor_sync(0xffffffffu, l1, 1);
    l1 += __shfl_xor_sync(0xffffffffu, l1, 2);
    if (c == 0) {
        lsum[wn * 64 + wm * 16 + r]     = l0;
        lsum[wn * 64 + wm * 16 + r + 8] = l1;
    }
    __syncthreads();

    if (wn == 0) {
        int row0 = wm * 16 + r;
        float inv0 = 1.f / (lsum[row0]     + lsum[64 + row0]);
        float inv1 = 1.f / (lsum[row0 + 8] + lsum[64 + row0 + 8]);
        const float* src = red + wm * 2048;
        __half* o0 = g_attn + (size_t)(bm * 64 + row0) * QS + h * 128;
        __half* o1 = g_attn + (size_t)(bm * 64 + row0 + 8) * QS + h * 128;
#pragma unroll
        for (int dn = 0; dn < 16; dn++) {
            int nc = dn * 8 + 2 * c;
            float2 s0 = *(const float2*)(src + r * 128 + nc);
            float2 s1 = *(const float2*)(src + (r + 8) * 128 + nc);
            *(__half2*)(o0 + nc) = __floats2half2_rn((acc_o[dn][0] + s0.x) * inv0,
                                                     (acc_o[dn][1] + s0.y) * inv0);
            *(__half2*)(o1 + nc) = __floats2half2_rn((acc_o[dn][2] + s1.x) * inv1,
                                                     (acc_o[dn][3] + s1.y) * inv1);
        }
    }
}

// ---------------- fp32 -> fp16 conversion (all three arrays + invf, one launch) ----------------
#define N4_HID  (TT * HIDDEN / 4)
#define N4_WQKV (QKVN * HIDDEN / 4)
#define N4_WO   (HIDDEN * QS / 4)
__global__ void h_conv_all(const float4* __restrict__ s0, uint2* __restrict__ d0,
                           const float4* __restrict__ s1, uint2* __restrict__ d1,
                           const float4* __restrict__ s2, uint2* __restrict__ d2) {
    if (blockIdx.x == 0 && threadIdx.x < 64)
        g_invf[threadIdx.x] = (float)exp(-(double)threadIdx.x * (log(10000.0) / 64.0));
    int i = blockIdx.x * 256 + threadIdx.x;
    int stride = gridDim.x * 256;
    int ntot = N4_HID + N4_WQKV + N4_WO;
    for (; i < ntot; i += stride) {
        const float4* s; uint2* d; int idx;
        if (i < N4_HID)              { s = s0; d = d0; idx = i; }
        else if (i < N4_HID + N4_WQKV) { s = s1; d = d1; idx = i - N4_HID; }
        else                         { s = s2; d = d2; idx = i - N4_HID - N4_WQKV; }
        float4 v = s[idx];
        __half2 lo = __floats2half2_rn(v.x, v.y);
        __half2 hi = __floats2half2_rn(v.z, v.w);
        uint2 o;
        o.x = *(unsigned*)&lo;
        o.y = *(unsigned*)&hi;
        d[idx] = o;
    }
}

// ---------------- launcher ----------------
extern "C" void kernel_launch(void* const* d_in, const int* in_sizes, int n_in,
                              void* d_out, int out_size)
{
    const int* positions = (const int*)d_in[0];   // int32 (JAX x64 disabled)
    const float* hidden = (const float*)d_in[1];
    const float* w_qkv  = (const float*)d_in[2];
    const float* w_o    = (const float*)d_in[3];
    const float* qw     = (const float*)d_in[4];
    const float* kw     = (const float*)d_in[5];
    float* out = (float*)d_out;

    __half *p_attn, *p_hidh, *p_wqkvh, *p_woh;
    cudaGetSymbolAddress((void**)&p_attn,  g_attn);
    cudaGetSymbolAddress((void**)&p_hidh,  g_hidh);
    cudaGetSymbolAddress((void**)&p_wqkvh, g_wqkvh);
    cudaGetSymbolAddress((void**)&p_woh,   g_woh);

    cudaFuncSetAttribute(gemm_h, cudaFuncAttributeMaxDynamicSharedMemorySize, SM_TOT);
    cudaFuncSetAttribute(flash_kernel, cudaFuncAttributeMaxDynamicSharedMemorySize, F3_TOT);

    // 0) fp16 conversions + invf (one launch)
    h_conv_all<<<2048, 256>>>((const float4*)hidden, (uint2*)p_hidh,
                              (const float4*)w_qkv,  (uint2*)p_wqkvh,
                              (const float4*)w_o,    (uint2*)p_woh);

    // 1) QKV projection with fused RMSNorm+RoPE+reorder epilogue
    gemm_h<<<dim3(QKVN / BN, TT / BM, 1), 256, SM_TOT>>>(
        p_hidh, p_wqkvh, nullptr, HIDDEN, HIDDEN, HIDDEN, 0, 1.0f,
        positions, qw, kw, 1);

    // 2) fused flash attention (64-row q-tiles, 2 CTA/SM, post-compute load issue) -> g_attn
    flash_kernel<<<1024, 256, F3_TOT>>>();

    // 3) output projection (fp32 out)
    gemm_h<<<dim3(HIDDEN / BN, TT / BM, 1), 256, SM_TOT>>>(
        p_attn, p_woh, out, QS, QS, QS, HIDDEN, 1.0f,
        nullptr, nullptr, nullptr, 0);
}

// round 17
// speedup vs baseline: 1.1068x; 1.0018x over previous
#include <cuda_runtime.h>
#include <cuda_fp16.h>
#include <math.h>
#include <float.h>
#include <stdint.h>

#define TT 2048
#define HIDDEN 2048
#define NH 32
#define NKV 4
#define HD 128
#define QS (NH*HD)        // 4096
#define KVS (NKV*HD)      // 512
#define QKVN (QS + 2*KVS) // 5120

// ---------------- scratch (static device globals; no allocs) ----------------
__device__ __half g_q   [(size_t)NH * TT * HD];   //  16 MB [h][t][d]  (pre-scaled by d^-1/2 * log2e)
__device__ __half g_k   [(size_t)NKV * TT * HD];  //   2 MB [kv][t][d]
__device__ __half g_vt  [(size_t)NKV * HD * TT];  //   2 MB [kv][d][t]
__device__ __half g_attn[(size_t)TT * QS];        //  16 MB [t][h*128+d]
__device__ __half g_hidh [(size_t)TT * HIDDEN];   //   8 MB fp16(hidden)
__device__ __half g_wqkvh[(size_t)QKVN * HIDDEN]; //  20 MB fp16(w_qkv)
__device__ __half g_woh  [(size_t)HIDDEN * QS];   //  16 MB fp16(w_o)
__device__ float  g_invf[64];

#define ATT_SCALE 0.08838834764831845f
#define LOG2E 1.4426950408889634f
#define EXP_SHIFT_L2 5.7707801635558535f   // 4 * log2(e)

// ---------------- helpers ----------------
__device__ __forceinline__ uint32_t smem_u32(const void* p) {
    uint32_t a;
    asm("{ .reg .u64 t; cvta.to.shared.u64 t, %1; cvt.u32.u64 %0, t; }" : "=r"(a) : "l"(p));
    return a;
}
__device__ __forceinline__ void cp16(uint32_t dst, const void* src) {
    asm volatile("cp.async.cg.shared.global [%0], [%1], 16;" :: "r"(dst), "l"(src));
}
__device__ __forceinline__ void mma_f16(float* d, const unsigned* a, const unsigned* b) {
    asm volatile(
        "mma.sync.aligned.m16n8k16.row.col.f32.f16.f16.f32 "
        "{%0,%1,%2,%3}, {%4,%5,%6,%7}, {%8,%9}, {%0,%1,%2,%3};\n"
        : "+f"(d[0]), "+f"(d[1]), "+f"(d[2]), "+f"(d[3])
        : "r"(a[0]), "r"(a[1]), "r"(a[2]), "r"(a[3]), "r"(b[0]), "r"(b[1]));
}
__device__ __forceinline__ void ldsm4(unsigned* r, uint32_t addr) {
    asm volatile("ldmatrix.sync.aligned.m8n8.x4.shared.b16 {%0,%1,%2,%3}, [%4];"
        : "=r"(r[0]), "=r"(r[1]), "=r"(r[2]), "=r"(r[3]) : "r"(addr));
}
__device__ __forceinline__ float ex2f(float x) {
    float y;
    asm("ex2.approx.f32 %0, %1;" : "=f"(y) : "f"(x));
    return y;
}

// ================= dense fp16 TN GEMM (128x128, 256 thr, 2 CTA/SM) =================
// Fully software-pipelined fragment loads: both A and B fragments double-buffered,
// every ldsm issued >=4 mmas ahead of first use.
#define STAGES 3
#define TILE_BYTES 16384
#define STAGE_BYTES 32768
#define SM_TOT (STAGES*STAGE_BYTES + 512)
#define BM 128
#define BN 128

// mode 0: plain fp32 C out
// mode 1: fused QKV epilogue: bn = head (0-31 q, 32-35 k, 36-39 v)
__global__ __launch_bounds__(256, 2) void gemm_h(
    const __half* __restrict__ A, const __half* __restrict__ B, float* __restrict__ C,
    int K, int lda, int ldb, int ldc, float scale,
    const int* __restrict__ positions, const float* __restrict__ qw,
    const float* __restrict__ kw, int mode)
{
    int bm = blockIdx.y, bn = blockIdx.x;

    extern __shared__ char smem[];
    uint32_t sbase = smem_u32(smem);

    int tid  = threadIdx.x;
    int warp = tid >> 5, lane = tid & 31;
    int wm = warp & 3, wn = warp >> 2;
    int r = lane >> 2, c = lane & 3;

    int arow_in = ((lane >> 3) & 1) * 8 + (lane & 7);
    int ahi = lane >> 4;
    int am7 = lane & 7;
    int bro = ((lane >> 4) << 3) + (lane & 7);
    int bcb = (lane >> 3) & 1;
    int bb7 = lane & 7;

    float acc[2][8][4];
#pragma unroll
    for (int i = 0; i < 2; i++)
#pragma unroll
        for (int j = 0; j < 8; j++)
#pragma unroll
            for (int k = 0; k < 4; k++) acc[i][j][k] = 0.f;

    int nkt = K >> 6;
    const __half* Ab = A + (long long)bm * BM * lda;
    const __half* Bb = B + (long long)bn * BN * ldb;

    int sm_ = tid >> 1;
    int scb = (tid & 1) * 4;
    long long arow = (long long)sm_ * lda;
    long long brow = (long long)sm_ * ldb;

    uint32_t arow0 = (uint32_t)(wm * 32 + arow_in);
    uint32_t arow1 = arow0 + 16;
    uint32_t brow0 = (uint32_t)(wn * 64 + bro);

#pragma unroll
    for (int p = 0; p < STAGES - 1; p++) {
        if (p < nkt) {
            int kb = p << 6;
            uint32_t aD = sbase + p * STAGE_BYTES + sm_ * 128;
            uint32_t bD = aD + TILE_BYTES;
            const __half* as = Ab + arow + kb + scb * 8;
            const __half* bs = Bb + brow + kb + scb * 8;
#pragma unroll
            for (int j = 0; j < 4; j++) {
                int sw = ((scb + j) ^ (sm_ & 7)) * 16;
                cp16(aD + sw, as + j * 8);
                cp16(bD + sw, bs + j * 8);
            }
        }
        asm volatile("cp.async.commit_group;" ::: "memory");
    }

    for (int kt = 0; kt < nkt; kt++) {
        asm volatile("cp.async.wait_group 1;" ::: "memory");
        __syncthreads();

        uint32_t sa  = sbase + (kt % STAGES) * STAGE_BYTES;
        uint32_t sbm = sa + TILE_BYTES;

        // ---- compute, fully pipelined fragment loads (A and B double-buffered) ----
        unsigned ac[2][4], an[2][4], bbc[4], bbn[4];
        ldsm4(ac[0], sa + arow0 * 128u + ((unsigned)((0 + ahi) ^ am7) << 4));
        ldsm4(ac[1], sa + arow1 * 128u + ((unsigned)((0 + ahi) ^ am7) << 4));
        ldsm4(bbc,   sbm + brow0 * 128u + ((unsigned)((0 + bcb) ^ bb7) << 4));
#pragma unroll
        for (int ks = 0; ks < 4; ks++) {
#pragma unroll
            for (int ntp = 0; ntp < 4; ntp++) {
                // prefetch slots
                if (ntp < 3) {
                    ldsm4(bbn, sbm + (brow0 + (ntp + 1) * 16) * 128u
                               + ((unsigned)((2 * ks + bcb) ^ bb7) << 4));
                } else if (ks < 3) {
                    ldsm4(bbn, sbm + brow0 * 128u
                               + ((unsigned)((2 * (ks + 1) + bcb) ^ bb7) << 4));
                }
                if (ks < 3) {
                    if (ntp == 1)
                        ldsm4(an[0], sa + arow0 * 128u
                                   + ((unsigned)((2 * (ks + 1) + ahi) ^ am7) << 4));
                    else if (ntp == 2)
                        ldsm4(an[1], sa + arow1 * 128u
                                   + ((unsigned)((2 * (ks + 1) + ahi) ^ am7) << 4));
                }
                mma_f16(acc[0][2 * ntp],     ac[0], bbc);
                mma_f16(acc[0][2 * ntp + 1], ac[0], bbc + 2);
                mma_f16(acc[1][2 * ntp],     ac[1], bbc);
                mma_f16(acc[1][2 * ntp + 1], ac[1], bbc + 2);
                bbc[0] = bbn[0]; bbc[1] = bbn[1]; bbc[2] = bbn[2]; bbc[3] = bbn[3];
            }
            if (ks < 3) {
#pragma unroll
                for (int q = 0; q < 4; q++) { ac[0][q] = an[0][q]; ac[1][q] = an[1][q]; }
            }
        }

        // ---- issue prefetch for stage kt+2 at END of iteration ----
        if (kt + STAGES - 1 < nkt) {
            int kn = kt + STAGES - 1;
            int kb = kn << 6;
            uint32_t aD = sbase + (kn % STAGES) * STAGE_BYTES + sm_ * 128;
            uint32_t bD = aD + TILE_BYTES;
            const __half* as = Ab + arow + kb + scb * 8;
            const __half* bs = Bb + brow + kb + scb * 8;
#pragma unroll
            for (int j = 0; j < 4; j++) {
                int sw = ((scb + j) ^ (sm_ & 7)) * 16;
                cp16(aD + sw, as + j * 8);
                cp16(bD + sw, bs + j * 8);
            }
        }
        asm volatile("cp.async.commit_group;" ::: "memory");
    }

    asm volatile("cp.async.wait_group 0;" ::: "memory");

    if (mode == 0) {
#pragma unroll
        for (int mt = 0; mt < 2; mt++) {
            int m0 = bm * BM + wm * 32 + mt * 16 + r;
#pragma unroll
            for (int nt = 0; nt < 8; nt++) {
                int n0 = bn * BN + wn * 64 + nt * 8 + 2 * c;
                *(float2*)(C + (long long)m0 * ldc + n0) =
                    make_float2(acc[mt][nt][0] * scale, acc[mt][nt][1] * scale);
                *(float2*)(C + (long long)(m0 + 8) * ldc + n0) =
                    make_float2(acc[mt][nt][2] * scale, acc[mt][nt][3] * scale);
            }
        }
        return;
    }

    // ---- fused QKV epilogue: acc -> smem buf (128 x 132 fp32), then norm/rope/transpose ----
    __syncthreads();
    float* buf = (float*)smem;
#pragma unroll
    for (int mt = 0; mt < 2; mt++) {
        int mrow = wm * 32 + mt * 16 + r;
#pragma unroll
        for (int nt = 0; nt < 8; nt++) {
            int nc = wn * 64 + nt * 8 + 2 * c;
            *(float2*)(buf + mrow * 132 + nc)       = make_float2(acc[mt][nt][0], acc[mt][nt][1]);
            *(float2*)(buf + (mrow + 8) * 132 + nc) = make_float2(acc[mt][nt][2], acc[mt][nt][3]);
        }
    }
    __syncthreads();

    int h = bn;
    if (h < 36) {
        int row = tid >> 1, half = tid & 1;
        int t = bm * BM + row;
        const float* own = buf + row * 132 + half * 64;
        const float* par = buf + row * 132 + (half ^ 1) * 64;

        float ss = 0.f;
#pragma unroll
        for (int i = 0; i < 16; i++) {
            float4 v = *(const float4*)(own + i * 4);
            ss += v.x * v.x + v.y * v.y + v.z * v.z + v.w * v.w;
        }
        ss += __shfl_xor_sync(0xffffffffu, ss, 1);
        float rinv = rsqrtf(ss * (1.f / 128.f) + 1e-6f);

        const float* w_ = (h < 32) ? qw : kw;
        float pos = (float)positions[t];
        float osc = (h < 32) ? (ATT_SCALE * LOG2E) : 1.f;
        float sgn = half ? 1.f : -1.f;
        __half* outp;
        if (h < 32) outp = g_q + ((size_t)h * TT + t) * HD + half * 64;
        else        outp = g_k + ((size_t)(h - 32) * TT + t) * HD + half * 64;

#pragma unroll 8
        for (int i = 0; i < 64; i += 2) {
            float cs0 = 0.f, sn0 = 0.f, cs1 = 0.f, sn1 = 0.f;
            if (!(lane & 1)) {
                float a0 = pos * g_invf[i], a1 = pos * g_invf[i + 1];
                cs0 = cosf(a0); sn0 = sinf(a0);
                cs1 = cosf(a1); sn1 = sinf(a1);
            }
            cs0 = __shfl_sync(0xffffffffu, cs0, lane & ~1);
            sn0 = __shfl_sync(0xffffffffu, sn0, lane & ~1);
            cs1 = __shfl_sync(0xffffffffu, cs1, lane & ~1);
            sn1 = __shfl_sync(0xffffffffu, sn1, lane & ~1);
            float y0 = own[i]     * rinv * w_[half * 64 + i];
            float y1 = own[i + 1] * rinv * w_[half * 64 + i + 1];
            float z0 = par[i]     * rinv * w_[(half ^ 1) * 64 + i];
            float z1 = par[i + 1] * rinv * w_[(half ^ 1) * 64 + i + 1];
            float o0 = (y0 * cs0 + sgn * z0 * sn0) * osc;
            float o1 = (y1 * cs1 + sgn * z1 * sn1) * osc;
            *(__half2*)(outp + i) = __floats2half2_rn(o0, o1);
        }
    } else {
        int d = tid >> 1, thalf = tid & 1;
        int kvh = h - 36;
        __half* vp = g_vt + ((size_t)kvh * HD + d) * TT + (size_t)bm * BM + thalf * 64;
#pragma unroll 8
        for (int j2 = 0; j2 < 64; j2 += 2) {
            float v0 = buf[(thalf * 64 + j2) * 132 + d];
            float v1 = buf[(thalf * 64 + j2 + 1) * 132 + d];
            *(__half2*)(vp + j2) = __floats2half2_rn(v0, v1);
        }
    }
}

// ================= fused flash attention: q64, 256 thr, 2 CTA/SM, loads issued post-compute =================
#define F3_Q  0
#define F3_K0 16384
#define F3_K1 49152
#define F3_V  81920
#define F3_L  114688
#define F3_TOT (F3_L + 512 + 128)

__device__ __forceinline__ void fl_load128(
    uint32_t sdst, const __half* src, long long ld, int tid)
{
#pragma unroll
    for (int i = 0; i < 8; i++) {
        int li = tid + 256 * i;
        int row = li >> 4, cc = li & 15;
        uint32_t dst = sdst + (cc >> 3) * 16384 + row * 128 + (((cc & 7) ^ (row & 7)) * 16);
        cp16(dst, src + (long long)row * ld + cc * 8);
    }
}

__global__ __launch_bounds__(256, 2) void flash_kernel()
{
    int b = blockIdx.x;
    int bm = 31 - (b >> 5);     // q-block of 64 rows; heavy first
    int h  = b & 31;
    int kvh = h >> 3;

    extern __shared__ char sm[];
    uint32_t sbase = smem_u32(sm);
    float* lsum = (float*)(sm + F3_L);

    int tid = threadIdx.x;
    int w = tid >> 5, lane = tid & 31;
    int wm = w & 3, wn = w >> 2;
    int r = lane >> 2, c = lane & 3;

    int am  = wm * 16 + ((lane >> 3) & 1) * 8 + (lane & 7);
    int am7 = am & 7;
    int ahi = lane >> 4;
    uint32_t aoff = (uint32_t)am * 128u;
    int bro = ((lane >> 4) << 3) + (lane & 7);
    int bcb = (lane >> 3) & 1;
    int bb7 = bro & 7;

    const __half* qsrc = g_q + ((size_t)h * TT + (size_t)bm * 64) * HD;
    const __half* ksrc = g_k + (size_t)kvh * TT * HD;
    const __half* vsrc = g_vt + (size_t)kvh * HD * TT;

    int nj = (bm >> 1) + 1;

#pragma unroll
    for (int i = 0; i < 4; i++) {
        int li = tid + 256 * i;
        int row = li >> 4, cc = li & 15;
        uint32_t dst = sbase + F3_Q + (cc >> 3) * 8192 + row * 128 + (((cc & 7) ^ (row & 7)) * 16);
        cp16(dst, qsrc + (long long)row * HD + cc * 8);
    }
    fl_load128(sbase + F3_K0, ksrc, HD, tid);
#pragma unroll
    for (int i = 0; i < 8; i++) {
        int li = tid + 256 * i;
        int row = li >> 4, cc = li & 15;
        uint32_t dst = sbase + F3_V + (cc >> 3) * 16384 + row * 128 + (((cc & 7) ^ (row & 7)) * 16);
        cp16(dst, vsrc + (size_t)row * TT + cc * 8);
    }
    asm volatile("cp.async.commit_group;" ::: "memory");
    if (nj > 1)
        fl_load128(sbase + F3_K1, ksrc + (size_t)128 * HD, HD, tid);
    asm volatile("cp.async.commit_group;" ::: "memory");

    float acc_o[16][4];
#pragma unroll
    for (int i = 0; i < 16; i++)
#pragma unroll
        for (int k = 0; k < 4; k++) acc_o[i][k] = 0.f;
    float l0a = 0.f, l0b = 0.f, l1a = 0.f, l1b = 0.f;

    int mrow0 = wm * 16 + r;

    for (int j = 0; j < nj; j++) {
        uint32_t kbuf = sbase + ((j & 1) ? F3_K1 : F3_K0);

        if (j == 0) { asm volatile("cp.async.wait_group 1;" ::: "memory"); }
        else        { asm volatile("cp.async.wait_group 2;" ::: "memory"); }
        __syncthreads();

        float acc_s[8][4];
#pragma unroll
        for (int i = 0; i < 8; i++)
#pragma unroll
            for (int k = 0; k < 4; k++) acc_s[i][k] = 0.f;

        uint32_t squ = sbase + F3_Q;
#pragma unroll
        for (int kt = 0; kt < 2; kt++) {
#pragma unroll
            for (int ks = 0; ks < 4; ks++) {
                unsigned a[4];
                ldsm4(a, squ + kt * 8192 + aoff + ((unsigned)((2 * ks + ahi) ^ am7) << 4));
#pragma unroll
                for (int ntp = 0; ntp < 4; ntp++) {
                    unsigned bb[4];
                    ldsm4(bb, kbuf + kt * 16384 + (unsigned)(wn * 64 + ntp * 16 + bro) * 128
                              + ((unsigned)((2 * ks + bcb) ^ bb7) << 4));
                    mma_f16(acc_s[2 * ntp],     a, bb);
                    mma_f16(acc_s[2 * ntp + 1], a, bb + 2);
                }
            }
        }

        asm volatile("cp.async.wait_group 1;" ::: "memory");
        __syncthreads();

        bool diag = (j == nj - 1);
        int lim = bm * 64 + mrow0 - j * 128;
        uint32_t svu = sbase + F3_V + wn * 16384;
#pragma unroll
        for (int ks = 0; ks < 4; ks++) {
            unsigned a[4];
#pragma unroll
            for (int q = 0; q < 2; q++) {
                int nt = 2 * ks + q;
                int n0 = wn * 64 + nt * 8 + 2 * c;
                float v0 = ex2f(acc_s[nt][0] - EXP_SHIFT_L2);
                float v1 = ex2f(acc_s[nt][1] - EXP_SHIFT_L2);
                float v2 = ex2f(acc_s[nt][2] - EXP_SHIFT_L2);
                float v3 = ex2f(acc_s[nt][3] - EXP_SHIFT_L2);
                if (diag) {
                    if (n0     > lim)     v0 = 0.f;
                    if (n0 + 1 > lim)     v1 = 0.f;
                    if (n0     > lim + 8) v2 = 0.f;
                    if (n0 + 1 > lim + 8) v3 = 0.f;
                }
                if (q == 0) { l0a += v0 + v1; l1a += v2 + v3; }
                else        { l0b += v0 + v1; l1b += v2 + v3; }
                __half2 h01 = __floats2half2_rn(v0, v1);
                __half2 h23 = __floats2half2_rn(v2, v3);
                a[2 * q]     = *(unsigned*)&h01;
                a[2 * q + 1] = *(unsigned*)&h23;
            }
#pragma unroll
            for (int dnp = 0; dnp < 8; dnp++) {
                unsigned bb[4];
                ldsm4(bb, svu + (unsigned)(dnp * 16 + bro) * 128
                          + ((unsigned)((2 * ks + bcb) ^ bb7) << 4));
                mma_f16(acc_o[2 * dnp],     a, bb);
                mma_f16(acc_o[2 * dnp + 1], a, bb + 2);
            }
        }

        __syncthreads();
        if (j + 1 < nj) {
#pragma unroll
            for (int i = 0; i < 8; i++) {
                int li = tid + 256 * i;
                int row = li >> 4, cc = li & 15;
                uint32_t dst = sbase + F3_V + (cc >> 3) * 16384 + row * 128
                             + (((cc & 7) ^ (row & 7)) * 16);
                cp16(dst, vsrc + (size_t)row * TT + (j + 1) * 128 + cc * 8);
            }
        }
        asm volatile("cp.async.commit_group;" ::: "memory");
        if (j + 2 < nj)
            fl_load128(sbase + (((j + 2) & 1) ? F3_K1 : F3_K0),
                       ksrc + (size_t)(j + 2) * 128 * HD, HD, tid);
        asm volatile("cp.async.commit_group;" ::: "memory");
    }

    asm volatile("cp.async.wait_group 0;" ::: "memory");

    __syncthreads();
    float* red = (float*)(sm + F3_K0);

    if (wn == 1) {
        float* dst = red + wm * 2048;
#pragma unroll
        for (int dn = 0; dn < 16; dn++) {
            *(float2*)(dst + r * 128 + dn * 8 + 2 * c)       = make_float2(acc_o[dn][0], acc_o[dn][1]);
            *(float2*)(dst + (r + 8) * 128 + dn * 8 + 2 * c) = make_float2(acc_o[dn][2], acc_o[dn][3]);
        }
    }
    float l0 = l0a + l0b, l1 = l1a + l1b;
    l0 += __shfl_xor_sync(0xffffffffu, l0, 1);
    l0 += __shfl_xor_sync(0xffffffffu, l0, 2);
    l1 += __shfl_xor_sync(0xffffffffu, l1, 1);
    l1 += __shfl_xor_sync(0xffffffffu, l1, 2);
    if (c == 0) {
        lsum[wn * 64 + wm * 16 + r]     = l0;
        lsum[wn * 64 + wm * 16 + r + 8] = l1;
    }
    __syncthreads();

    if (wn == 0) {
        int row0 = wm * 16 + r;
        float inv0 = 1.f / (lsum[row0]     + lsum[64 + row0]);
        float inv1 = 1.f / (lsum[row0 + 8] + lsum[64 + row0 + 8]);
        const float* src = red + wm * 2048;
        __half* o0 = g_attn + (size_t)(bm * 64 + row0) * QS + h * 128;
        __half* o1 = g_attn + (size_t)(bm * 64 + row0 + 8) * QS + h * 128;
#pragma unroll
        for (int dn = 0; dn < 16; dn++) {
            int nc = dn * 8 + 2 * c;
            float2 s0 = *(const float2*)(src + r * 128 + nc);
            float2 s1 = *(const float2*)(src + (r + 8) * 128 + nc);
            *(__half2*)(o0 + nc) = __floats2half2_rn((acc_o[dn][0] + s0.x) * inv0,
                                                     (acc_o[dn][1] + s0.y) * inv0);
            *(__half2*)(o1 + nc) = __floats2half2_rn((acc_o[dn][2] + s1.x) * inv1,
                                                     (acc_o[dn][3] + s1.y) * inv1);
        }
    }
}

// ---------------- fp32 -> fp16 conversion (all three arrays + invf, one launch) ----------------
#define N4_HID  (TT * HIDDEN / 4)
#define N4_WQKV (QKVN * HIDDEN / 4)
#define N4_WO   (HIDDEN * QS / 4)
__global__ void h_conv_all(const float4* __restrict__ s0, uint2* __restrict__ d0,
                           const float4* __restrict__ s1, uint2* __restrict__ d1,
                           const float4* __restrict__ s2, uint2* __restrict__ d2) {
    if (blockIdx.x == 0 && threadIdx.x < 64)
        g_invf[threadIdx.x] = (float)exp(-(double)threadIdx.x * (log(10000.0) / 64.0));
    int i = blockIdx.x * 256 + threadIdx.x;
    int stride = gridDim.x * 256;
    int ntot = N4_HID + N4_WQKV + N4_WO;
    for (; i < ntot; i += stride) {
        const float4* s; uint2* d; int idx;
        if (i < N4_HID)              { s = s0; d = d0; idx = i; }
        else if (i < N4_HID + N4_WQKV) { s = s1; d = d1; idx = i - N4_HID; }
        else                         { s = s2; d = d2; idx = i - N4_HID - N4_WQKV; }
        float4 v = s[idx];
        __half2 lo = __floats2half2_rn(v.x, v.y);
        __half2 hi = __floats2half2_rn(v.z, v.w);
        uint2 o;
        o.x = *(unsigned*)&lo;
        o.y = *(unsigned*)&hi;
        d[idx] = o;
    }
}

// ---------------- launcher ----------------
extern "C" void kernel_launch(void* const* d_in, const int* in_sizes, int n_in,
                              void* d_out, int out_size)
{
    const int* positions = (const int*)d_in[0];   // int32 (JAX x64 disabled)
    const float* hidden = (const float*)d_in[1];
    const float* w_qkv  = (const float*)d_in[2];
    const float* w_o    = (const float*)d_in[3];
    const float* qw     = (const float*)d_in[4];
    const float* kw     = (const float*)d_in[5];
    float* out = (float*)d_out;

    __half *p_attn, *p_hidh, *p_wqkvh, *p_woh;
    cudaGetSymbolAddress((void**)&p_attn,  g_attn);
    cudaGetSymbolAddress((void**)&p_hidh,  g_hidh);
    cudaGetSymbolAddress((void**)&p_wqkvh, g_wqkvh);
    cudaGetSymbolAddress((void**)&p_woh,   g_woh);

    cudaFuncSetAttribute(gemm_h, cudaFuncAttributeMaxDynamicSharedMemorySize, SM_TOT);
    cudaFuncSetAttribute(flash_kernel, cudaFuncAttributeMaxDynamicSharedMemorySize, F3_TOT);

    // 0) fp16 conversions + invf (one launch)
    h_conv_all<<<2048, 256>>>((const float4*)hidden, (uint2*)p_hidh,
                              (const float4*)w_qkv,  (uint2*)p_wqkvh,
                              (const float4*)w_o,    (uint2*)p_woh);

    // 1) QKV projection with fused RMSNorm+RoPE+reorder epilogue
    gemm_h<<<dim3(QKVN / BN, TT / BM, 1), 256, SM_TOT>>>(
        p_hidh, p_wqkvh, nullptr, HIDDEN, HIDDEN, HIDDEN, 0, 1.0f,
        positions, qw, kw, 1);

    // 2) fused flash attention (64-row q-tiles, 2 CTA/SM, post-compute load issue) -> g_attn
    flash_kernel<<<1024, 256, F3_TOT>>>();

    // 3) output projection (fp32 out)
    gemm_h<<<dim3(HIDDEN / BN, TT / BM, 1), 256, SM_TOT>>>(
        p_attn, p_woh, out, QS, QS, QS, HIDDEN, 1.0f,
        nullptr, nullptr, nullptr, 0);
}